// round 2
// baseline (speedup 1.0000x reference)
#include <cuda_runtime.h>
#include <math.h>

#define HWSZ 50176           // 224*224
#define BB   4
#define CC   256
#define NHH  8
#define HDD  32

// ---------------- scratch (device globals; no runtime allocation) ----------------
__device__ float g_qkv [(size_t)BB * 768 * HWSZ];   // [B][768][HW]
__device__ float g_h   [(size_t)BB * CC  * HWSZ];   // hidden, reused
__device__ float g_psi [(size_t)BB * CC  * HWSZ];
__device__ float g_gk  [(size_t)BB * CC  * HWSZ];
__device__ float g_gv  [(size_t)BB * CC  * HWSZ];
__device__ float g_f   [(size_t)BB * CC  * HWSZ];
__device__ float g_mean[BB * CC];
__device__ float g_cvec[BB * CC];

// ---------------- global mean of G over H,W per (b,c) ----------------
__global__ void mean_kernel(const float* __restrict__ G, float* __restrict__ out) {
    const int bc = blockIdx.x;  // 0..1023
    const float4* p = (const float4*)(G + (size_t)bc * HWSZ);
    float s = 0.f;
    for (int i = threadIdx.x; i < HWSZ / 4; i += blockDim.x) {
        float4 v = p[i];
        s += (v.x + v.y) + (v.z + v.w);
    }
    __shared__ float sm[256];
    sm[threadIdx.x] = s;
    __syncthreads();
    for (int k = 128; k > 0; k >>= 1) {
        if (threadIdx.x < k) sm[threadIdx.x] += sm[threadIdx.x + k];
        __syncthreads();
    }
    if (threadIdx.x == 0) out[bc] = sm[0] * (1.f / HWSZ);
}

// ---------------- cvec[b][oc] = 0.5 * Wout[oc,:] . gmean[b,:] + bout[oc] ----------------
__global__ void cvec_kernel(const float* __restrict__ Wout, const float* __restrict__ bout,
                            const float* __restrict__ gmean, float* __restrict__ cvec) {
    __shared__ float gm[CC];
    const int b = blockIdx.x, oc = threadIdx.x;
    gm[oc] = gmean[b * CC + oc];
    __syncthreads();
    float s = 0.f;
    #pragma unroll 8
    for (int c = 0; c < CC; ++c) s += Wout[(size_t)oc * CC + c] * gm[c];
    cvec[b * CC + oc] = 0.5f * s + bout[oc];
}

// ---------------- generic 1x1-conv GEMM: Y[b][oc][hw] = epi( W[oc,:] . X[b,:,hw] + bias ) ----------------
enum { EPI_BIAS = 0, EPI_RELU = 1, EPI_SIG = 2, EPI_SIG_GATE = 3, EPI_OUT = 4 };

__device__ __forceinline__ float sigmoidf_(float x) { return 1.f / (1.f + __expf(-x)); }

template<int EPI, bool GENX>
__global__ void __launch_bounds__(256, 2)
gemm1x1(const float* __restrict__ Wm, const float* __restrict__ bias,
        const float* __restrict__ X, float* __restrict__ Y,
        const float* __restrict__ aux,              // psi (gate) or cvec (out)
        const float* __restrict__ vsrc,             // GENX: scalar V per pixel
        const float* __restrict__ wp1, const float* __restrict__ bp1,
        int OC)
{
    const int b    = blockIdx.z;
    const int pix0 = blockIdx.x << 7;   // 128 pixels
    const int oc0  = blockIdx.y << 7;   // 128 out channels
    const int tid  = threadIdx.x;

    __shared__ float Ws[2][8][128];
    __shared__ float Xs[2][8][128];
    __shared__ float vs[128];

    const int w_oc = tid >> 1;
    const int w_k4 = (tid & 1) << 2;
    const int x_k  = tid >> 5;          // 0..7
    const int x_p  = (tid & 31) << 2;   // 0..124

    const float* Wp = Wm + (size_t)(oc0 + w_oc) * CC + w_k4;
    const float* Xp = nullptr;
    if (!GENX) Xp = X + (size_t)b * CC * HWSZ + (size_t)x_k * HWSZ + pix0 + x_p;

    if (GENX) {
        if (tid < 128) vs[tid] = vsrc[(size_t)b * HWSZ + pix0 + tid];
    }
    __syncthreads();

    float4 wreg = *(const float4*)Wp;
    float4 xreg;
    float wk = 0.f, bk = 0.f;
    if (GENX) { wk = wp1[x_k]; bk = bp1[x_k]; }
    else       xreg = *(const float4*)Xp;

    const int ty = tid >> 4;   // oc dir (0..15)
    const int tx = tid & 15;   // pixel dir (0..15)

    float acc[8][8];
    #pragma unroll
    for (int i = 0; i < 8; ++i)
        #pragma unroll
        for (int j = 0; j < 8; ++j) acc[i][j] = 0.f;

    #pragma unroll 1
    for (int kt = 0; kt < 32; ++kt) {
        const int buf = kt & 1;
        // store prefetched tile
        Ws[buf][w_k4 + 0][w_oc] = wreg.x;
        Ws[buf][w_k4 + 1][w_oc] = wreg.y;
        Ws[buf][w_k4 + 2][w_oc] = wreg.z;
        Ws[buf][w_k4 + 3][w_oc] = wreg.w;
        if (GENX) {
            Xs[buf][x_k][x_p + 0] = fmaxf(vs[x_p + 0] * wk + bk, 0.f);
            Xs[buf][x_k][x_p + 1] = fmaxf(vs[x_p + 1] * wk + bk, 0.f);
            Xs[buf][x_k][x_p + 2] = fmaxf(vs[x_p + 2] * wk + bk, 0.f);
            Xs[buf][x_k][x_p + 3] = fmaxf(vs[x_p + 3] * wk + bk, 0.f);
        } else {
            *(float4*)&Xs[buf][x_k][x_p] = xreg;
        }
        __syncthreads();
        // prefetch next k-tile into registers (latency hidden by compute)
        if (kt < 31) {
            const int k0 = (kt + 1) << 3;
            wreg = *(const float4*)(Wp + k0);
            if (GENX) { wk = wp1[k0 + x_k]; bk = bp1[k0 + x_k]; }
            else       xreg = *(const float4*)(Xp + (size_t)k0 * HWSZ);
        }
        // compute 128x128x8 with 8x8 micro-tiles
        #pragma unroll
        for (int kk = 0; kk < 8; ++kk) {
            float a[8], bbv[8];
            *(float4*)(a)     = *(const float4*)&Ws[buf][kk][ty * 8];
            *(float4*)(a + 4) = *(const float4*)&Ws[buf][kk][ty * 8 + 4];
            *(float4*)(bbv)     = *(const float4*)&Xs[buf][kk][tx * 8];
            *(float4*)(bbv + 4) = *(const float4*)&Xs[buf][kk][tx * 8 + 4];
            #pragma unroll
            for (int i = 0; i < 8; ++i)
                #pragma unroll
                for (int j = 0; j < 8; ++j)
                    acc[i][j] += a[i] * bbv[j];
        }
    }

    // epilogue
    const size_t pixbase = (size_t)pix0 + (tx << 3);
    #pragma unroll
    for (int i = 0; i < 8; ++i) {
        const int oc = oc0 + ty * 8 + i;
        float badd = 0.f;
        if (EPI != EPI_OUT) badd = bias[oc];
        float* yrow = Y + ((size_t)b * OC + oc) * HWSZ + pixbase;
        const float* arow = nullptr;
        float cv = 0.f;
        if (EPI == EPI_SIG_GATE) arow = aux + ((size_t)b * CC + oc) * HWSZ + pixbase;
        if (EPI == EPI_OUT)      cv   = aux[b * CC + oc];
        float r[8];
        #pragma unroll
        for (int j = 0; j < 8; ++j) {
            float y = acc[i][j] + badd;
            if      (EPI == EPI_RELU)     y = fmaxf(y, 0.f);
            else if (EPI == EPI_SIG)      y = sigmoidf_(y);
            else if (EPI == EPI_SIG_GATE) y = sigmoidf_(y) * (1.f - arow[j]);
            else if (EPI == EPI_OUT)      y = 0.5f * acc[i][j] + cv;
            r[j] = y;
        }
        *(float4*)yrow       = *(float4*)r;
        *(float4*)(yrow + 4) = *(float4*)(r + 4);
    }
}

// ---------------- windowed attention: one block per (window, head) ----------------
__global__ void __launch_bounds__(128)
attn_kernel(const float* __restrict__ qkv, const float* __restrict__ gk,
            const float* __restrict__ gv, float* __restrict__ f)
{
    const int w   = blockIdx.x;           // 0..4095
    const int h   = blockIdx.y;           // 0..7
    const int b   = w >> 10;
    const int wy  = (w >> 5) & 31;
    const int wx  = w & 31;
    const int tid = threadIdx.x;

    __shared__ float Qs[49 * 33];
    __shared__ float Ks[49 * 33];
    __shared__ float Vs[49 * 33];
    __shared__ float S [49 * 49];

    const int row0 = wy * 7, col0 = wx * 7;

    for (int e = tid; e < 49 * 32; e += 128) {
        const int d = e / 49, n = e - d * 49;
        const int hw = (row0 + n / 7) * 224 + col0 + (n % 7);
        const int ch = h * 32 + d;
        const size_t qi = ((size_t)b * 768 + ch) * HWSZ + hw;
        const size_t gi = ((size_t)b * 256 + ch) * HWSZ + hw;
        Qs[n * 33 + d] = qkv[qi];
        Ks[n * 33 + d] = qkv[qi + (size_t)256 * HWSZ] * gk[gi];
        Vs[n * 33 + d] = qkv[qi + (size_t)512 * HWSZ] * gv[gi];
    }
    __syncthreads();

    const float scale = 0.17677669529663687f;   // 32^-0.5
    for (int e = tid; e < 49 * 49; e += 128) {
        const int i = e / 49, j = e - i * 49;
        float s = 0.f;
        #pragma unroll
        for (int d = 0; d < 32; ++d) s += Qs[i * 33 + d] * Ks[j * 33 + d];
        S[e] = s * scale;
    }
    __syncthreads();

    if (tid < 49) {
        float m = -1e30f;
        for (int j = 0; j < 49; ++j) m = fmaxf(m, S[tid * 49 + j]);
        float sum = 0.f;
        for (int j = 0; j < 49; ++j) {
            float ev = __expf(S[tid * 49 + j] - m);
            S[tid * 49 + j] = ev;
            sum += ev;
        }
        const float inv = 1.f / sum;
        for (int j = 0; j < 49; ++j) S[tid * 49 + j] *= inv;
    }
    __syncthreads();

    for (int e = tid; e < 49 * 32; e += 128) {
        const int d = e / 49, n = e - d * 49;
        float s = 0.f;
        #pragma unroll
        for (int m2 = 0; m2 < 49; ++m2) s += S[n * 49 + m2] * Vs[m2 * 33 + d];
        const int hw = (row0 + n / 7) * 224 + col0 + (n % 7);
        f[((size_t)b * 256 + h * 32 + d) * HWSZ + hw] = s;
    }
}

// ---------------- launcher ----------------
extern "C" void kernel_launch(void* const* d_in, const int* in_sizes, int n_in,
                              void* d_out, int out_size) {
    (void)in_sizes; (void)n_in; (void)out_size;
    const float* G    = (const float*)d_in[0];
    // d_in[1] = p_sal (unused in tau=0 path)
    const float* Vin  = (const float*)d_in[2];
    const float* Z    = (const float*)d_in[3];
    const float* Wqkv = (const float*)d_in[4];
    const float* bqkv = (const float*)d_in[5];
    const float* Wout = (const float*)d_in[6];
    const float* bout = (const float*)d_in[7];
    const float* Wk1  = (const float*)d_in[8];
    const float* bk1  = (const float*)d_in[9];
    const float* Wk2  = (const float*)d_in[10];
    const float* bk2  = (const float*)d_in[11];
    const float* Wv1  = (const float*)d_in[12];
    const float* bv1  = (const float*)d_in[13];
    const float* Wv2  = (const float*)d_in[14];
    const float* bv2  = (const float*)d_in[15];
    const float* Wp1  = (const float*)d_in[16];
    const float* bp1  = (const float*)d_in[17];
    const float* Wp2  = (const float*)d_in[18];
    const float* bp2  = (const float*)d_in[19];
    float* out = (float*)d_out;

    float *qkv, *hbuf, *psi, *gk, *gv, *fbuf, *gmean, *cvec;
    cudaGetSymbolAddress((void**)&qkv,   g_qkv);
    cudaGetSymbolAddress((void**)&hbuf,  g_h);
    cudaGetSymbolAddress((void**)&psi,   g_psi);
    cudaGetSymbolAddress((void**)&gk,    g_gk);
    cudaGetSymbolAddress((void**)&gv,    g_gv);
    cudaGetSymbolAddress((void**)&fbuf,  g_f);
    cudaGetSymbolAddress((void**)&gmean, g_mean);
    cudaGetSymbolAddress((void**)&cvec,  g_cvec);

    const dim3 blk(256);
    const dim3 g256(392, 2, 4);   // HW/128, 256/128, B
    const dim3 g768(392, 6, 4);   // HW/128, 768/128, B

    mean_kernel<<<1024, 256>>>(G, gmean);
    cvec_kernel<<<4, 256>>>(Wout, bout, gmean, cvec);

    // psi = sigmoid(Wp2 @ relu(v*wp1+bp1) + bp2)   (X generated on the fly)
    gemm1x1<EPI_SIG, true><<<g256, blk>>>(Wp2, bp2, nullptr, psi, nullptr, Vin, Wp1, bp1, 256);

    // gk = sigmoid(Wk2 @ relu(Wk1@Z+bk1) + bk2) * (1-psi)
    gemm1x1<EPI_RELU,     false><<<g256, blk>>>(Wk1, bk1, Z,    hbuf, nullptr, nullptr, nullptr, nullptr, 256);
    gemm1x1<EPI_SIG_GATE, false><<<g256, blk>>>(Wk2, bk2, hbuf, gk,   psi,     nullptr, nullptr, nullptr, 256);

    // gv likewise
    gemm1x1<EPI_RELU,     false><<<g256, blk>>>(Wv1, bv1, Z,    hbuf, nullptr, nullptr, nullptr, nullptr, 256);
    gemm1x1<EPI_SIG_GATE, false><<<g256, blk>>>(Wv2, bv2, hbuf, gv,   psi,     nullptr, nullptr, nullptr, 256);

    // qkv = Wqkv @ G + bqkv
    gemm1x1<EPI_BIAS, false><<<g768, blk>>>(Wqkv, bqkv, G, qkv, nullptr, nullptr, nullptr, nullptr, 768);

    // windowed attention -> f
    attn_kernel<<<dim3(4096, 8), 128>>>(qkv, gk, gv, fbuf);

    // out = 0.5 * Wout @ f + cvec   (cvec holds 0.5*Wout@mean(G) + bout)
    gemm1x1<EPI_OUT, false><<<g256, blk>>>(Wout, nullptr, fbuf, out, cvec, nullptr, nullptr, nullptr, 256);
}

// round 3
// speedup vs baseline: 1.0204x; 1.0204x over previous
#include <cuda_runtime.h>
#include <math.h>

#define HWSZ 50176           // 224*224
#define BB   4
#define CC   256
#define NHH  8
#define HDD  32

typedef unsigned long long ull;

// ---------------- scratch (device globals; no runtime allocation) ----------------
__device__ float g_qkv [(size_t)BB * 768 * HWSZ];   // [B][768][HW]
__device__ float g_h   [(size_t)BB * CC  * HWSZ];   // hidden, reused
__device__ float g_psi [(size_t)BB * CC  * HWSZ];
__device__ float g_gk  [(size_t)BB * CC  * HWSZ];
__device__ float g_gv  [(size_t)BB * CC  * HWSZ];
__device__ float g_f   [(size_t)BB * CC  * HWSZ];
__device__ float g_mean[BB * CC];
__device__ float g_cvec[BB * CC];

// ---------------- packed f32x2 helpers (sm_103a FFMA2 path) ----------------
__device__ __forceinline__ ull dup2_(float x) {
    ull r; asm("mov.b64 %0, {%1, %1};" : "=l"(r) : "f"(x)); return r;
}
__device__ __forceinline__ ull ffma2_(ull a, ull b, ull c) {
    ull d; asm("fma.rn.f32x2 %0, %1, %2, %3;" : "=l"(d) : "l"(a), "l"(b), "l"(c)); return d;
}
__device__ __forceinline__ void unpack2_(ull v, float& lo, float& hi) {
    asm("mov.b64 {%0, %1}, %2;" : "=f"(lo), "=f"(hi) : "l"(v));
}

// ---------------- global mean of G over H,W per (b,c) ----------------
__global__ void mean_kernel(const float* __restrict__ G, float* __restrict__ out) {
    const int bc = blockIdx.x;  // 0..1023
    const float4* p = (const float4*)(G + (size_t)bc * HWSZ);
    float s = 0.f;
    for (int i = threadIdx.x; i < HWSZ / 4; i += blockDim.x) {
        float4 v = p[i];
        s += (v.x + v.y) + (v.z + v.w);
    }
    __shared__ float sm[256];
    sm[threadIdx.x] = s;
    __syncthreads();
    for (int k = 128; k > 0; k >>= 1) {
        if (threadIdx.x < k) sm[threadIdx.x] += sm[threadIdx.x + k];
        __syncthreads();
    }
    if (threadIdx.x == 0) out[bc] = sm[0] * (1.f / HWSZ);
}

// ---------------- cvec[b][oc] = 0.5 * Wout[oc,:] . gmean[b,:] + bout[oc] ----------------
__global__ void cvec_kernel(const float* __restrict__ Wout, const float* __restrict__ bout,
                            const float* __restrict__ gmean, float* __restrict__ cvec) {
    __shared__ float gm[CC];
    const int b = blockIdx.x, oc = threadIdx.x;
    gm[oc] = gmean[b * CC + oc];
    __syncthreads();
    float s = 0.f;
    #pragma unroll 8
    for (int c = 0; c < CC; ++c) s += Wout[(size_t)oc * CC + c] * gm[c];
    cvec[b * CC + oc] = 0.5f * s + bout[oc];
}

// ---------------- generic 1x1-conv GEMM: Y[b][oc][hw] = epi( W[oc,:] . X[b,:,hw] + bias ) ----------------
enum { EPI_BIAS = 0, EPI_RELU = 1, EPI_SIG = 2, EPI_SIG_GATE = 3, EPI_OUT = 4 };

__device__ __forceinline__ float sigmoidf_(float x) { return 1.f / (1.f + __expf(-x)); }

template<int EPI, bool GENX>
__global__ void __launch_bounds__(256, 2)
gemm1x1(const float* __restrict__ Wm, const float* __restrict__ bias,
        const float* __restrict__ X, float* __restrict__ Y,
        const float* __restrict__ aux,              // psi (gate) or cvec (out)
        const float* __restrict__ vsrc,             // GENX: scalar V per pixel
        const float* __restrict__ wp1, const float* __restrict__ bp1,
        int OC)
{
    const int b    = blockIdx.z;
    const int pix0 = blockIdx.x << 7;   // 128 pixels
    const int oc0  = blockIdx.y << 7;   // 128 out channels
    const int tid  = threadIdx.x;

    __shared__ float Ws[2][8][128];
    __shared__ float Xs[2][8][128];
    __shared__ float vs[128];

    const int w_oc = tid >> 1;
    const int w_k4 = (tid & 1) << 2;
    const int x_k  = tid >> 5;          // 0..7
    const int x_p  = (tid & 31) << 2;   // 0..124

    const float* Wp = Wm + (size_t)(oc0 + w_oc) * CC + w_k4;
    const float* Xp = nullptr;
    if (!GENX) Xp = X + (size_t)b * CC * HWSZ + (size_t)x_k * HWSZ + pix0 + x_p;

    if (GENX) {
        if (tid < 128) vs[tid] = vsrc[(size_t)b * HWSZ + pix0 + tid];
    }
    __syncthreads();

    float4 wreg = *(const float4*)Wp;
    float4 xreg;
    float wk = 0.f, bk = 0.f;
    if (GENX) { wk = wp1[x_k]; bk = bp1[x_k]; }
    else       xreg = *(const float4*)Xp;

    const int ty = tid >> 4;   // oc dir (0..15)
    const int tx = tid & 15;   // pixel dir (0..15)

    // accumulators packed pairwise along the pixel axis: acc2[i][j2] = (acc[i][2j2], acc[i][2j2+1])
    ull acc2[8][4];
    #pragma unroll
    for (int i = 0; i < 8; ++i)
        #pragma unroll
        for (int j = 0; j < 4; ++j) acc2[i][j] = 0ull;

    #pragma unroll 1
    for (int kt = 0; kt < 32; ++kt) {
        const int buf = kt & 1;
        // store prefetched tile
        Ws[buf][w_k4 + 0][w_oc] = wreg.x;
        Ws[buf][w_k4 + 1][w_oc] = wreg.y;
        Ws[buf][w_k4 + 2][w_oc] = wreg.z;
        Ws[buf][w_k4 + 3][w_oc] = wreg.w;
        if (GENX) {
            Xs[buf][x_k][x_p + 0] = fmaxf(vs[x_p + 0] * wk + bk, 0.f);
            Xs[buf][x_k][x_p + 1] = fmaxf(vs[x_p + 1] * wk + bk, 0.f);
            Xs[buf][x_k][x_p + 2] = fmaxf(vs[x_p + 2] * wk + bk, 0.f);
            Xs[buf][x_k][x_p + 3] = fmaxf(vs[x_p + 3] * wk + bk, 0.f);
        } else {
            *(float4*)&Xs[buf][x_k][x_p] = xreg;
        }
        __syncthreads();
        // prefetch next k-tile into registers (latency hidden by compute)
        if (kt < 31) {
            const int k0 = (kt + 1) << 3;
            wreg = *(const float4*)(Wp + k0);
            if (GENX) { wk = wp1[k0 + x_k]; bk = bp1[k0 + x_k]; }
            else       xreg = *(const float4*)(Xp + (size_t)k0 * HWSZ);
        }
        // compute 128x128x8 with 8x8 micro-tiles; inner product via packed FFMA2
        #pragma unroll
        for (int kk = 0; kk < 8; ++kk) {
            float a[8];
            *(float4*)(a)     = *(const float4*)&Ws[buf][kk][ty * 8];
            *(float4*)(a + 4) = *(const float4*)&Ws[buf][kk][ty * 8 + 4];
            // 8 consecutive pixels as four packed f32x2 operands (LDS.128 pairs)
            const ulonglong2* xp2 = (const ulonglong2*)&Xs[buf][kk][tx * 8];
            ulonglong2 u0 = xp2[0];
            ulonglong2 u1 = xp2[1];
            #pragma unroll
            for (int i = 0; i < 8; ++i) {
                ull ad = dup2_(a[i]);
                acc2[i][0] = ffma2_(ad, u0.x, acc2[i][0]);
                acc2[i][1] = ffma2_(ad, u0.y, acc2[i][1]);
                acc2[i][2] = ffma2_(ad, u1.x, acc2[i][2]);
                acc2[i][3] = ffma2_(ad, u1.y, acc2[i][3]);
            }
        }
    }

    // epilogue
    const size_t pixbase = (size_t)pix0 + (tx << 3);
    #pragma unroll
    for (int i = 0; i < 8; ++i) {
        const int oc = oc0 + ty * 8 + i;
        float badd = 0.f;
        if (EPI != EPI_OUT) badd = bias[oc];
        float* yrow = Y + ((size_t)b * OC + oc) * HWSZ + pixbase;
        const float* arow = nullptr;
        float cv = 0.f;
        if (EPI == EPI_SIG_GATE) arow = aux + ((size_t)b * CC + oc) * HWSZ + pixbase;
        if (EPI == EPI_OUT)      cv   = aux[b * CC + oc];
        float acc[8];
        #pragma unroll
        for (int j2 = 0; j2 < 4; ++j2) unpack2_(acc2[i][j2], acc[2 * j2], acc[2 * j2 + 1]);
        float r[8];
        #pragma unroll
        for (int j = 0; j < 8; ++j) {
            float y = acc[j] + badd;
            if      (EPI == EPI_RELU)     y = fmaxf(y, 0.f);
            else if (EPI == EPI_SIG)      y = sigmoidf_(y);
            else if (EPI == EPI_SIG_GATE) y = sigmoidf_(y) * (1.f - arow[j]);
            else if (EPI == EPI_OUT)      y = 0.5f * acc[j] + cv;
            r[j] = y;
        }
        *(float4*)yrow       = *(float4*)r;
        *(float4*)(yrow + 4) = *(float4*)(r + 4);
    }
}

// ---------------- windowed attention: one block per (window, head) ----------------
__global__ void __launch_bounds__(128)
attn_kernel(const float* __restrict__ qkv, const float* __restrict__ gk,
            const float* __restrict__ gv, float* __restrict__ f)
{
    const int w   = blockIdx.x;           // 0..4095
    const int h   = blockIdx.y;           // 0..7
    const int b   = w >> 10;
    const int wy  = (w >> 5) & 31;
    const int wx  = w & 31;
    const int tid = threadIdx.x;

    __shared__ float Qs[49 * 33];
    __shared__ float Ks[49 * 33];
    __shared__ float Vs[49 * 33];
    __shared__ float S [49 * 49];

    const int row0 = wy * 7, col0 = wx * 7;

    for (int e = tid; e < 49 * 32; e += 128) {
        const int d = e / 49, n = e - d * 49;
        const int hw = (row0 + n / 7) * 224 + col0 + (n % 7);
        const int ch = h * 32 + d;
        const size_t qi = ((size_t)b * 768 + ch) * HWSZ + hw;
        const size_t gi = ((size_t)b * 256 + ch) * HWSZ + hw;
        Qs[n * 33 + d] = qkv[qi];
        Ks[n * 33 + d] = qkv[qi + (size_t)256 * HWSZ] * gk[gi];
        Vs[n * 33 + d] = qkv[qi + (size_t)512 * HWSZ] * gv[gi];
    }
    __syncthreads();

    const float scale = 0.17677669529663687f;   // 32^-0.5
    for (int e = tid; e < 49 * 49; e += 128) {
        const int i = e / 49, j = e - i * 49;
        float s = 0.f;
        #pragma unroll
        for (int d = 0; d < 32; ++d) s += Qs[i * 33 + d] * Ks[j * 33 + d];
        S[e] = s * scale;
    }
    __syncthreads();

    if (tid < 49) {
        float m = -1e30f;
        for (int j = 0; j < 49; ++j) m = fmaxf(m, S[tid * 49 + j]);
        float sum = 0.f;
        for (int j = 0; j < 49; ++j) {
            float ev = __expf(S[tid * 49 + j] - m);
            S[tid * 49 + j] = ev;
            sum += ev;
        }
        const float inv = 1.f / sum;
        for (int j = 0; j < 49; ++j) S[tid * 49 + j] *= inv;
    }
    __syncthreads();

    for (int e = tid; e < 49 * 32; e += 128) {
        const int d = e / 49, n = e - d * 49;
        float s = 0.f;
        #pragma unroll
        for (int m2 = 0; m2 < 49; ++m2) s += S[n * 49 + m2] * Vs[m2 * 33 + d];
        const int hw = (row0 + n / 7) * 224 + col0 + (n % 7);
        f[((size_t)b * 256 + h * 32 + d) * HWSZ + hw] = s;
    }
}

// ---------------- launcher ----------------
extern "C" void kernel_launch(void* const* d_in, const int* in_sizes, int n_in,
                              void* d_out, int out_size) {
    (void)in_sizes; (void)n_in; (void)out_size;
    const float* G    = (const float*)d_in[0];
    // d_in[1] = p_sal (unused in tau=0 path)
    const float* Vin  = (const float*)d_in[2];
    const float* Z    = (const float*)d_in[3];
    const float* Wqkv = (const float*)d_in[4];
    const float* bqkv = (const float*)d_in[5];
    const float* Wout = (const float*)d_in[6];
    const float* bout = (const float*)d_in[7];
    const float* Wk1  = (const float*)d_in[8];
    const float* bk1  = (const float*)d_in[9];
    const float* Wk2  = (const float*)d_in[10];
    const float* bk2  = (const float*)d_in[11];
    const float* Wv1  = (const float*)d_in[12];
    const float* bv1  = (const float*)d_in[13];
    const float* Wv2  = (const float*)d_in[14];
    const float* bv2  = (const float*)d_in[15];
    const float* Wp1  = (const float*)d_in[16];
    const float* bp1  = (const float*)d_in[17];
    const float* Wp2  = (const float*)d_in[18];
    const float* bp2  = (const float*)d_in[19];
    float* out = (float*)d_out;

    float *qkv, *hbuf, *psi, *gk, *gv, *fbuf, *gmean, *cvec;
    cudaGetSymbolAddress((void**)&qkv,   g_qkv);
    cudaGetSymbolAddress((void**)&hbuf,  g_h);
    cudaGetSymbolAddress((void**)&psi,   g_psi);
    cudaGetSymbolAddress((void**)&gk,    g_gk);
    cudaGetSymbolAddress((void**)&gv,    g_gv);
    cudaGetSymbolAddress((void**)&fbuf,  g_f);
    cudaGetSymbolAddress((void**)&gmean, g_mean);
    cudaGetSymbolAddress((void**)&cvec,  g_cvec);

    const dim3 blk(256);
    const dim3 g256(392, 2, 4);   // HW/128, 256/128, B
    const dim3 g768(392, 6, 4);   // HW/128, 768/128, B

    mean_kernel<<<1024, 256>>>(G, gmean);
    cvec_kernel<<<4, 256>>>(Wout, bout, gmean, cvec);

    // psi = sigmoid(Wp2 @ relu(v*wp1+bp1) + bp2)   (X generated on the fly)
    gemm1x1<EPI_SIG, true><<<g256, blk>>>(Wp2, bp2, nullptr, psi, nullptr, Vin, Wp1, bp1, 256);

    // gk = sigmoid(Wk2 @ relu(Wk1@Z+bk1) + bk2) * (1-psi)
    gemm1x1<EPI_RELU,     false><<<g256, blk>>>(Wk1, bk1, Z,    hbuf, nullptr, nullptr, nullptr, nullptr, 256);
    gemm1x1<EPI_SIG_GATE, false><<<g256, blk>>>(Wk2, bk2, hbuf, gk,   psi,     nullptr, nullptr, nullptr, 256);

    // gv likewise
    gemm1x1<EPI_RELU,     false><<<g256, blk>>>(Wv1, bv1, Z,    hbuf, nullptr, nullptr, nullptr, nullptr, 256);
    gemm1x1<EPI_SIG_GATE, false><<<g256, blk>>>(Wv2, bv2, hbuf, gv,   psi,     nullptr, nullptr, nullptr, 256);

    // qkv = Wqkv @ G + bqkv
    gemm1x1<EPI_BIAS, false><<<g768, blk>>>(Wqkv, bqkv, G, qkv, nullptr, nullptr, nullptr, nullptr, 768);

    // windowed attention -> f
    attn_kernel<<<dim3(4096, 8), 128>>>(qkv, gk, gv, fbuf);

    // out = 0.5 * Wout @ f + cvec   (cvec holds 0.5*Wout@mean(G) + bout)
    gemm1x1<EPI_OUT, false><<<g256, blk>>>(Wout, nullptr, fbuf, out, cvec, nullptr, nullptr, nullptr, 256);
}

// round 5
// speedup vs baseline: 1.3097x; 1.2835x over previous
#include <cuda_runtime.h>
#include <cuda_bf16.h>
#include <math.h>
#include <stdint.h>

#define HWSZ 50176           // 224*224
#define BB   4
#define CC   256

// ================= scratch (device globals; no runtime allocation) =================
__device__ float g_qkv [(size_t)BB * 768 * HWSZ];   // [B][768][HW] fp32
__device__ float g_psi [(size_t)BB * CC  * HWSZ];
__device__ float g_gk  [(size_t)BB * CC  * HWSZ];
__device__ float g_gv  [(size_t)BB * CC  * HWSZ];
__device__ float g_mean[BB * CC];
__device__ float g_cvec[BB * CC];
// bf16 hi/lo transposed operand buffers [B][HW][C]
__device__ __nv_bfloat16 g_tah[(size_t)BB * HWSZ * CC];
__device__ __nv_bfloat16 g_tal[(size_t)BB * HWSZ * CC];
__device__ __nv_bfloat16 g_tbh[(size_t)BB * HWSZ * CC];
__device__ __nv_bfloat16 g_tbl[(size_t)BB * HWSZ * CC];
__device__ __nv_bfloat16 g_tch[(size_t)BB * HWSZ * CC];
__device__ __nv_bfloat16 g_tcl[(size_t)BB * HWSZ * CC];
// split weights: rows [qkv 0..768 | k1 | k2 | v1 | v2 | p2 | out], 256 cols each
__device__ __nv_bfloat16 g_wsh[2304 * 256];
__device__ __nv_bfloat16 g_wsl[2304 * 256];

// ================= helpers =================
__device__ __forceinline__ uint32_t smem_u32(const void* p) {
    uint32_t a;
    asm("{ .reg .u64 t; cvta.to.shared.u64 t, %1; cvt.u32.u64 %0, t; }" : "=r"(a) : "l"(p));
    return a;
}
__device__ __forceinline__ void cp16(uint32_t dst, const void* src) {
    asm volatile("cp.async.cg.shared.global [%0], [%1], 16;" :: "r"(dst), "l"(src) : "memory");
}
__device__ __forceinline__ void cp_commit() {
    asm volatile("cp.async.commit_group;" ::: "memory");
}
__device__ __forceinline__ void mma_bf16(float* c, const uint32_t* a, uint32_t b0, uint32_t b1) {
    asm volatile(
        "mma.sync.aligned.m16n8k16.row.col.f32.bf16.bf16.f32 "
        "{%0,%1,%2,%3}, {%4,%5,%6,%7}, {%8,%9}, {%0,%1,%2,%3};"
        : "+f"(c[0]), "+f"(c[1]), "+f"(c[2]), "+f"(c[3])
        : "r"(a[0]), "r"(a[1]), "r"(a[2]), "r"(a[3]), "r"(b0), "r"(b1));
}
__device__ __forceinline__ float sigmoidf_(float x) { return 1.f / (1.f + __expf(-x)); }

// ================= small kernels =================
__global__ void mean_kernel(const float* __restrict__ G, float* __restrict__ out) {
    const int bc = blockIdx.x;
    const float4* p = (const float4*)(G + (size_t)bc * HWSZ);
    float s = 0.f;
    for (int i = threadIdx.x; i < HWSZ / 4; i += blockDim.x) {
        float4 v = p[i];
        s += (v.x + v.y) + (v.z + v.w);
    }
    __shared__ float sm[256];
    sm[threadIdx.x] = s;
    __syncthreads();
    for (int k = 128; k > 0; k >>= 1) {
        if (threadIdx.x < k) sm[threadIdx.x] += sm[threadIdx.x + k];
        __syncthreads();
    }
    if (threadIdx.x == 0) out[bc] = sm[0] * (1.f / HWSZ);
}

__global__ void cvec_kernel(const float* __restrict__ Wout, const float* __restrict__ bout,
                            const float* __restrict__ gmean, float* __restrict__ cvec) {
    __shared__ float gm[CC];
    const int b = blockIdx.x, oc = threadIdx.x;
    gm[oc] = gmean[b * CC + oc];
    __syncthreads();
    float s = 0.f;
    #pragma unroll 8
    for (int c = 0; c < CC; ++c) s += Wout[(size_t)oc * CC + c] * gm[c];
    cvec[b * CC + oc] = 0.5f * s + bout[oc];
}

__global__ void wsplit(const float* __restrict__ W, __nv_bfloat16* __restrict__ Th,
                       __nv_bfloat16* __restrict__ Tl, int n) {
    int i = blockIdx.x * 256 + threadIdx.x;
    if (i < n) {
        float v = W[i];
        __nv_bfloat16 h = __float2bfloat16(v);
        Th[i] = h;
        Tl[i] = __float2bfloat16(v - __bfloat162float(h));
    }
}

// transpose X[b][C][HW] -> Th/Tl[b][HW][C] with hi/lo split
__global__ void tsplit(const float* __restrict__ X, __nv_bfloat16* __restrict__ Th,
                       __nv_bfloat16* __restrict__ Tl) {
    __shared__ float t[32][33];
    const int b = blockIdx.z, k0 = blockIdx.y * 32, p0 = blockIdx.x * 32;
    const int tx = threadIdx.x, ty = threadIdx.y;
    const float* src = X + ((size_t)b * CC + k0) * HWSZ + p0;
    #pragma unroll
    for (int r = 0; r < 4; ++r)
        t[ty + r * 8][tx] = src[(size_t)(ty + r * 8) * HWSZ + tx];
    __syncthreads();
    #pragma unroll
    for (int r = 0; r < 4; ++r) {
        const int p = ty + r * 8;
        float v = t[tx][p];
        __nv_bfloat16 h = __float2bfloat16(v);
        __nv_bfloat16 l = __float2bfloat16(v - __bfloat162float(h));
        size_t o = ((size_t)b * HWSZ + p0 + p) * CC + k0 + tx;
        Th[o] = h;
        Tl[o] = l;
    }
}

// psi-branch input: relu(V[pix]*wp1[c]+bp1[c]) -> [b][HW][C] hi/lo
__global__ void psix(const float* __restrict__ V, const float* __restrict__ wp1,
                     const float* __restrict__ bp1,
                     __nv_bfloat16* __restrict__ Th, __nv_bfloat16* __restrict__ Tl) {
    const int b = blockIdx.y, tid = threadIdx.x;
    const float w = wp1[tid], bi = bp1[tid];
    const int p0 = blockIdx.x * 8;
    #pragma unroll
    for (int r = 0; r < 8; ++r) {
        float v = V[(size_t)b * HWSZ + p0 + r];
        float x = fmaxf(v * w + bi, 0.f);
        __nv_bfloat16 h = __float2bfloat16(x);
        __nv_bfloat16 l = __float2bfloat16(x - __bfloat162float(h));
        size_t o = ((size_t)b * HWSZ + p0 + r) * CC + tid;
        Th[o] = h;
        Tl[o] = l;
    }
}

// ================= HMMA GEMM =================
// D[m][n] = epi( sum_k A[m][k]*B[n][k] ), K=256, tile 128x128, 8 warps (4m x 2n),
// 3-term compensated bf16: Ah*Bh + Ah*Bl + Al*Bh, fp32 accum.
// SWAP=false: m = oc (weights on A side), n = pixels; fp32 output [b][OC][HW].
// SWAP=true : m = pixels (X on A side), n = oc;  bf16 hi/lo output [b][HW][CC] (EPI_RELU_T).
enum { EPI_BIAS = 0, EPI_RELU_T = 1, EPI_SIG = 2, EPI_SIG_GATE = 3, EPI_OUT = 4 };

#define KC        32                       // k per chunk
#define ROW_W     20                       // smem words per row (32 bf16 + 8B pad = 80B)
#define BUF_W     (128 * ROW_W)            // 2560 words per buffer
#define STAGE_W   (4 * BUF_W)              // Ah, Al, Bh, Bl
#define SMEM_BYTES (2 * STAGE_W * 4)       // 81920

template<int EPI, bool SWAP>
__global__ void __launch_bounds__(256, 1)
gemm_hmma(const __nv_bfloat16* __restrict__ Ah_, const __nv_bfloat16* __restrict__ Al_,
          const __nv_bfloat16* __restrict__ Bh_, const __nv_bfloat16* __restrict__ Bl_,
          const float* __restrict__ bias, float* __restrict__ Yf,
          __nv_bfloat16* __restrict__ Yh, __nv_bfloat16* __restrict__ Yl,
          const float* __restrict__ aux, int OC)
{
    extern __shared__ char dsm[];
    uint32_t* smw = (uint32_t*)dsm;
    const uint32_t smb = smem_u32(dsm);

    const int b = blockIdx.z;
    const int tid = threadIdx.x, wid = tid >> 5, lane = tid & 31;
    const int g = lane >> 2, t = lane & 3;
    const int warpM = wid & 3, warpN = wid >> 2;

    const size_t mrow0 = SWAP ? ((size_t)b * HWSZ + (size_t)blockIdx.x * 128)
                              : (size_t)blockIdx.y * 128;
    const size_t nrow0 = SWAP ? (size_t)blockIdx.y * 128
                              : ((size_t)b * HWSZ + (size_t)blockIdx.x * 128);

    // cp.async mapping: buf = tid>>6 (Ah, Al, Bh, Bl), 2 rows per thread, 4x16B per row
    const int buf = tid >> 6, sl = tid & 63;
    const __nv_bfloat16* gsrc =
        (buf == 0) ? Ah_ + mrow0 * CC :
        (buf == 1) ? Al_ + mrow0 * CC :
        (buf == 2) ? Bh_ + nrow0 * CC :
                     Bl_ + nrow0 * CC;
    const int r0 = sl * 2;
    const uint32_t dbase = smb + (uint32_t)buf * (BUF_W * 4);

    auto load_chunk = [&](int c) {
        const uint32_t st = dbase + (uint32_t)(c & 1) * (STAGE_W * 4);
        const int k0 = c * KC;
        #pragma unroll
        for (int rr = 0; rr < 2; ++rr) {
            const int r = r0 + rr;
            const uint32_t drow = st + (uint32_t)r * 80;
            const __nv_bfloat16* srow = gsrc + (size_t)r * CC + k0;
            #pragma unroll
            for (int q = 0; q < 4; ++q)
                cp16(drow + q * 16, srow + q * 8);
        }
        cp_commit();
    };

    float acc[2][8][4];
    #pragma unroll
    for (int mi = 0; mi < 2; ++mi)
        #pragma unroll
        for (int ni = 0; ni < 8; ++ni)
            #pragma unroll
            for (int u = 0; u < 4; ++u) acc[mi][ni][u] = 0.f;

    load_chunk(0);
    load_chunk(1);

    #pragma unroll 1
    for (int c = 0; c < 8; ++c) {
        if (c < 7) asm volatile("cp.async.wait_group 1;" ::: "memory");
        else       asm volatile("cp.async.wait_group 0;" ::: "memory");
        __syncthreads();

        const uint32_t sw = (uint32_t)(c & 1) * STAGE_W;   // word offset of stage
        #pragma unroll
        for (int k16 = 0; k16 < 2; ++k16) {
            const int kw = k16 * 8 + t;
            uint32_t ah[2][4], al[2][4];
            #pragma unroll
            for (int mi = 0; mi < 2; ++mi) {
                const int mr = warpM * 32 + mi * 16 + g;
                ah[mi][0] = smw[sw + mr * ROW_W + kw];
                ah[mi][1] = smw[sw + (mr + 8) * ROW_W + kw];
                ah[mi][2] = smw[sw + mr * ROW_W + kw + 4];
                ah[mi][3] = smw[sw + (mr + 8) * ROW_W + kw + 4];
                al[mi][0] = smw[sw + BUF_W + mr * ROW_W + kw];
                al[mi][1] = smw[sw + BUF_W + (mr + 8) * ROW_W + kw];
                al[mi][2] = smw[sw + BUF_W + mr * ROW_W + kw + 4];
                al[mi][3] = smw[sw + BUF_W + (mr + 8) * ROW_W + kw + 4];
            }
            #pragma unroll
            for (int ni = 0; ni < 8; ++ni) {
                const int nr = warpN * 64 + ni * 8 + g;
                const uint32_t bh0 = smw[sw + 2 * BUF_W + nr * ROW_W + kw];
                const uint32_t bh1 = smw[sw + 2 * BUF_W + nr * ROW_W + kw + 4];
                const uint32_t bl0 = smw[sw + 3 * BUF_W + nr * ROW_W + kw];
                const uint32_t bl1 = smw[sw + 3 * BUF_W + nr * ROW_W + kw + 4];
                #pragma unroll
                for (int mi = 0; mi < 2; ++mi) {
                    mma_bf16(acc[mi][ni], ah[mi], bh0, bh1);
                    mma_bf16(acc[mi][ni], ah[mi], bl0, bl1);
                    mma_bf16(acc[mi][ni], al[mi], bh0, bh1);
                }
            }
        }
        __syncthreads();
        if (c + 2 < 8) load_chunk(c + 2);
    }

    // ================= epilogue =================
    #pragma unroll
    for (int mi = 0; mi < 2; ++mi) {
        #pragma unroll
        for (int r2 = 0; r2 < 2; ++r2) {
            const int mrow = warpM * 32 + mi * 16 + g + r2 * 8;   // row within 128-tile
            if (!SWAP) {
                const int oc = (int)blockIdx.y * 128 + mrow;
                const size_t pixb = (size_t)b * HWSZ + (size_t)blockIdx.x * 128;
                float badd = 0.f, cv = 0.f;
                if (EPI != EPI_OUT) badd = bias[oc];
                if (EPI == EPI_OUT) cv = aux[b * CC + oc];
                float* yrow = Yf + ((size_t)b * OC + oc) * HWSZ + (size_t)blockIdx.x * 128;
                const float* arow = (EPI == EPI_SIG_GATE)
                    ? aux + ((size_t)b * CC + oc) * HWSZ + (size_t)blockIdx.x * 128 : nullptr;
                #pragma unroll
                for (int ni = 0; ni < 8; ++ni) {
                    const int ncol = warpN * 64 + ni * 8 + t * 2;
                    float v0 = acc[mi][ni][r2 * 2 + 0];
                    float v1 = acc[mi][ni][r2 * 2 + 1];
                    if (EPI == EPI_BIAS) { v0 += badd; v1 += badd; }
                    else if (EPI == EPI_SIG) { v0 = sigmoidf_(v0 + badd); v1 = sigmoidf_(v1 + badd); }
                    else if (EPI == EPI_SIG_GATE) {
                        float2 aa = *(const float2*)(arow + ncol);
                        v0 = sigmoidf_(v0 + badd) * (1.f - aa.x);
                        v1 = sigmoidf_(v1 + badd) * (1.f - aa.y);
                    } else if (EPI == EPI_OUT) { v0 = 0.5f * v0 + cv; v1 = 0.5f * v1 + cv; }
                    float2 r; r.x = v0; r.y = v1;
                    *(float2*)(yrow + ncol) = r;
                }
                (void)pixb;
            } else {
                // SWAP: rows are pixels, cols are oc; relu then bf16 hi/lo split
                const size_t prow = (size_t)b * HWSZ + (size_t)blockIdx.x * 128 + mrow;
                #pragma unroll
                for (int ni = 0; ni < 8; ++ni) {
                    const int oc = (int)blockIdx.y * 128 + warpN * 64 + ni * 8 + t * 2;
                    float v0 = fmaxf(acc[mi][ni][r2 * 2 + 0] + bias[oc], 0.f);
                    float v1 = fmaxf(acc[mi][ni][r2 * 2 + 1] + bias[oc + 1], 0.f);
                    __nv_bfloat16 h0 = __float2bfloat16(v0);
                    __nv_bfloat16 h1 = __float2bfloat16(v1);
                    __nv_bfloat16 l0 = __float2bfloat16(v0 - __bfloat162float(h0));
                    __nv_bfloat16 l1 = __float2bfloat16(v1 - __bfloat162float(h1));
                    __nv_bfloat162 hh; hh.x = h0; hh.y = h1;
                    __nv_bfloat162 ll; ll.x = l0; ll.y = l1;
                    *(__nv_bfloat162*)(Yh + prow * CC + oc) = hh;
                    *(__nv_bfloat162*)(Yl + prow * CC + oc) = ll;
                }
            }
        }
    }
}

// ================= windowed attention (writes bf16 hi/lo transposed f) =================
__global__ void __launch_bounds__(128)
attn_kernel(const float* __restrict__ qkv, const float* __restrict__ gk,
            const float* __restrict__ gv,
            __nv_bfloat16* __restrict__ fth, __nv_bfloat16* __restrict__ ftl)
{
    const int w = blockIdx.x, h = blockIdx.y;
    const int b = w >> 10, wy = (w >> 5) & 31, wx = w & 31;
    const int tid = threadIdx.x;

    __shared__ float Qs[49 * 33];
    __shared__ float Ks[49 * 33];
    __shared__ float Vs[49 * 33];
    __shared__ float S [49 * 49];

    const int row0 = wy * 7, col0 = wx * 7;

    for (int e = tid; e < 49 * 32; e += 128) {
        const int d = e / 49, n = e - d * 49;
        const int hw = (row0 + n / 7) * 224 + col0 + (n % 7);
        const int ch = h * 32 + d;
        const size_t qi = ((size_t)b * 768 + ch) * HWSZ + hw;
        const size_t gi = ((size_t)b * 256 + ch) * HWSZ + hw;
        Qs[n * 33 + d] = qkv[qi];
        Ks[n * 33 + d] = qkv[qi + (size_t)256 * HWSZ] * gk[gi];
        Vs[n * 33 + d] = qkv[qi + (size_t)512 * HWSZ] * gv[gi];
    }
    __syncthreads();

    const float scale = 0.17677669529663687f;
    for (int e = tid; e < 49 * 49; e += 128) {
        const int i = e / 49, j = e - i * 49;
        float s = 0.f;
        #pragma unroll
        for (int d = 0; d < 32; ++d) s += Qs[i * 33 + d] * Ks[j * 33 + d];
        S[e] = s * scale;
    }
    __syncthreads();

    if (tid < 49) {
        float m = -1e30f;
        for (int j = 0; j < 49; ++j) m = fmaxf(m, S[tid * 49 + j]);
        float sum = 0.f;
        for (int j = 0; j < 49; ++j) {
            float ev = __expf(S[tid * 49 + j] - m);
            S[tid * 49 + j] = ev;
            sum += ev;
        }
        const float inv = 1.f / sum;
        for (int j = 0; j < 49; ++j) S[tid * 49 + j] *= inv;
    }
    __syncthreads();

    for (int e = tid; e < 49 * 32; e += 128) {
        const int n = e >> 5, d = e & 31;
        float s = 0.f;
        #pragma unroll
        for (int m2 = 0; m2 < 49; ++m2) s += S[n * 49 + m2] * Vs[m2 * 33 + d];
        const int hw = (row0 + n / 7) * 224 + col0 + (n % 7);
        const size_t o = ((size_t)b * HWSZ + hw) * CC + h * 32 + d;
        __nv_bfloat16 hh = __float2bfloat16(s);
        fth[o] = hh;
        ftl[o] = __float2bfloat16(s - __bfloat162float(hh));
    }
}

// ================= launcher =================
extern "C" void kernel_launch(void* const* d_in, const int* in_sizes, int n_in,
                              void* d_out, int out_size) {
    (void)in_sizes; (void)n_in; (void)out_size;
    const float* G    = (const float*)d_in[0];
    const float* Vin  = (const float*)d_in[2];
    const float* Z    = (const float*)d_in[3];
    const float* Wqkv = (const float*)d_in[4];
    const float* bqkv = (const float*)d_in[5];
    const float* Wout = (const float*)d_in[6];
    const float* bout = (const float*)d_in[7];
    const float* Wk1  = (const float*)d_in[8];
    const float* bk1  = (const float*)d_in[9];
    const float* Wk2  = (const float*)d_in[10];
    const float* bk2  = (const float*)d_in[11];
    const float* Wv1  = (const float*)d_in[12];
    const float* bv1  = (const float*)d_in[13];
    const float* Wv2  = (const float*)d_in[14];
    const float* bv2  = (const float*)d_in[15];
    const float* Wp1  = (const float*)d_in[16];
    const float* bp1  = (const float*)d_in[17];
    const float* Wp2  = (const float*)d_in[18];
    const float* bp2  = (const float*)d_in[19];
    float* out = (float*)d_out;

    float *qkv, *psi, *gk, *gv, *gmean, *cvec;
    __nv_bfloat16 *tah, *tal, *tbh, *tbl, *tch, *tcl, *wsh, *wsl;
    cudaGetSymbolAddress((void**)&qkv,   g_qkv);
    cudaGetSymbolAddress((void**)&psi,   g_psi);
    cudaGetSymbolAddress((void**)&gk,    g_gk);
    cudaGetSymbolAddress((void**)&gv,    g_gv);
    cudaGetSymbolAddress((void**)&gmean, g_mean);
    cudaGetSymbolAddress((void**)&cvec,  g_cvec);
    cudaGetSymbolAddress((void**)&tah,   g_tah);
    cudaGetSymbolAddress((void**)&tal,   g_tal);
    cudaGetSymbolAddress((void**)&tbh,   g_tbh);
    cudaGetSymbolAddress((void**)&tbl,   g_tbl);
    cudaGetSymbolAddress((void**)&tch,   g_tch);
    cudaGetSymbolAddress((void**)&tcl,   g_tcl);
    cudaGetSymbolAddress((void**)&wsh,   g_wsh);
    cudaGetSymbolAddress((void**)&wsl,   g_wsl);

    cudaFuncSetAttribute(gemm_hmma<EPI_BIAS,     false>, cudaFuncAttributeMaxDynamicSharedMemorySize, SMEM_BYTES);
    cudaFuncSetAttribute(gemm_hmma<EPI_RELU_T,   true>,  cudaFuncAttributeMaxDynamicSharedMemorySize, SMEM_BYTES);
    cudaFuncSetAttribute(gemm_hmma<EPI_SIG,      false>, cudaFuncAttributeMaxDynamicSharedMemorySize, SMEM_BYTES);
    cudaFuncSetAttribute(gemm_hmma<EPI_SIG_GATE, false>, cudaFuncAttributeMaxDynamicSharedMemorySize, SMEM_BYTES);
    cudaFuncSetAttribute(gemm_hmma<EPI_OUT,      false>, cudaFuncAttributeMaxDynamicSharedMemorySize, SMEM_BYTES);

    const size_t OFF_QKV = 0;
    const size_t OFF_K1  = (size_t)768  * 256;
    const size_t OFF_K2  = (size_t)1024 * 256;
    const size_t OFF_V1  = (size_t)1280 * 256;
    const size_t OFF_V2  = (size_t)1536 * 256;
    const size_t OFF_P2  = (size_t)1792 * 256;
    const size_t OFF_OUT = (size_t)2048 * 256;

    mean_kernel<<<1024, 256>>>(G, gmean);
    cvec_kernel<<<4, 256>>>(Wout, bout, gmean, cvec);

    wsplit<<<768, 256>>>(Wqkv, wsh + OFF_QKV, wsl + OFF_QKV, 768 * 256);
    wsplit<<<256, 256>>>(Wk1,  wsh + OFF_K1,  wsl + OFF_K1,  256 * 256);
    wsplit<<<256, 256>>>(Wk2,  wsh + OFF_K2,  wsl + OFF_K2,  256 * 256);
    wsplit<<<256, 256>>>(Wv1,  wsh + OFF_V1,  wsl + OFF_V1,  256 * 256);
    wsplit<<<256, 256>>>(Wv2,  wsh + OFF_V2,  wsl + OFF_V2,  256 * 256);
    wsplit<<<256, 256>>>(Wp2,  wsh + OFF_P2,  wsl + OFF_P2,  256 * 256);
    wsplit<<<256, 256>>>(Wout, wsh + OFF_OUT, wsl + OFF_OUT, 256 * 256);

    const dim3 tgrid(HWSZ / 32, CC / 32, BB), tblk(32, 8);
    tsplit<<<tgrid, tblk>>>(G, tah, tal);
    tsplit<<<tgrid, tblk>>>(Z, tbh, tbl);
    psix<<<dim3(HWSZ / 8, BB), 256>>>(Vin, Wp1, bp1, tch, tcl);

    const dim3 gN(392, 2, BB);    // n tiles x oc tiles(256) x B
    const dim3 gQ(392, 6, BB);    // qkv: 768 oc

    // psi = sigmoid(Wp2 @ relu(v*wp1+bp1) + bp2)  -> fp32 [b][C][HW]
    gemm_hmma<EPI_SIG, false><<<gN, 256, SMEM_BYTES>>>(
        wsh + OFF_P2, wsl + OFF_P2, tch, tcl, bp2, psi, nullptr, nullptr, nullptr, 256);

    // h = relu(Wk1@Z+bk1) -> bf16 hi/lo [b][HW][C] (swapped tile)
    gemm_hmma<EPI_RELU_T, true><<<gN, 256, SMEM_BYTES>>>(
        tbh, tbl, wsh + OFF_K1, wsl + OFF_K1, bk1, nullptr, tch, tcl, nullptr, 256);
    // gk = sigmoid(Wk2@h+bk2)*(1-psi)
    gemm_hmma<EPI_SIG_GATE, false><<<gN, 256, SMEM_BYTES>>>(
        wsh + OFF_K2, wsl + OFF_K2, tch, tcl, bk2, gk, nullptr, nullptr, psi, 256);

    // gv likewise
    gemm_hmma<EPI_RELU_T, true><<<gN, 256, SMEM_BYTES>>>(
        tbh, tbl, wsh + OFF_V1, wsl + OFF_V1, bv1, nullptr, tch, tcl, nullptr, 256);
    gemm_hmma<EPI_SIG_GATE, false><<<gN, 256, SMEM_BYTES>>>(
        wsh + OFF_V2, wsl + OFF_V2, tch, tcl, bv2, gv, nullptr, nullptr, psi, 256);

    // qkv = Wqkv @ G + bqkv -> fp32
    gemm_hmma<EPI_BIAS, false><<<gQ, 256, SMEM_BYTES>>>(
        wsh + OFF_QKV, wsl + OFF_QKV, tah, tal, bqkv, qkv, nullptr, nullptr, nullptr, 768);

    // attention -> transposed bf16 hi/lo f
    attn_kernel<<<dim3(4096, 8), 128>>>(qkv, gk, gv, tch, tcl);

    // out = 0.5 * Wout @ f + cvec
    gemm_hmma<EPI_OUT, false><<<gN, 256, SMEM_BYTES>>>(
        wsh + OFF_OUT, wsl + OFF_OUT, tch, tcl, nullptr, out, nullptr, nullptr, cvec, 256);
}

// round 7
// speedup vs baseline: 2.6748x; 2.0422x over previous
#include <cuda_runtime.h>
#include <cuda_fp16.h>
#include <math.h>
#include <stdint.h>

#define HWSZ 50176           // 224*224
#define BB   4
#define CC   256
#define KP   264             // padded row stride (fp16): 528B = 33*16B (K=256 data + 16B pad)
#define KPB  528

// ================= scratch (device globals) =================
__device__ __half g_qkv[(size_t)BB * 768 * HWSZ];   // [B][768][HW] fp16
__device__ __half g_psi[(size_t)BB * CC  * HWSZ];
__device__ __half g_gk [(size_t)BB * CC  * HWSZ];
__device__ __half g_gv [(size_t)BB * CC  * HWSZ];
__device__ float  g_mean[BB * CC];
__device__ float  g_cvec[BB * CC];
// fp16 transposed operands, padded rows [B][HW][KP]
__device__ __half g_ta[(size_t)BB * HWSZ * KP];
__device__ __half g_tb[(size_t)BB * HWSZ * KP];
__device__ __half g_tc[(size_t)BB * HWSZ * KP];
// padded fp16 weights: rows [qkv 768 | k1 | k2 | v1 | v2 | p2 | out] x KP
__device__ __half g_wp[2304 * KP];

// ================= PTX helpers =================
__device__ __forceinline__ uint32_t smem_u32(const void* p) {
    uint32_t a;
    asm("{ .reg .u64 t; cvta.to.shared.u64 t, %1; cvt.u32.u64 %0, t; }" : "=r"(a) : "l"(p));
    return a;
}
__device__ __forceinline__ void mbar_init(uint32_t a, uint32_t cnt) {
    asm volatile("mbarrier.init.shared.b64 [%0], %1;" :: "r"(a), "r"(cnt) : "memory");
}
__device__ __forceinline__ void expect_tx(uint32_t mbar, uint32_t bytes) {
    asm volatile("mbarrier.arrive.expect_tx.shared.b64 _, [%0], %1;" :: "r"(mbar), "r"(bytes) : "memory");
}
__device__ __forceinline__ void bulk_g2s(uint32_t dst, const void* src, uint32_t bytes, uint32_t mbar) {
    asm volatile("cp.async.bulk.shared::cluster.global.mbarrier::complete_tx::bytes [%0], [%1], %2, [%3];"
                 :: "r"(dst), "l"(src), "r"(bytes), "r"(mbar) : "memory");
}
__device__ __forceinline__ void mbar_wait(uint32_t mbar, uint32_t parity) {
    asm volatile(
        "{\n\t.reg .pred P;\n"
        "W_%=:\n\t"
        "mbarrier.try_wait.parity.acquire.cta.shared::cta.b64 P, [%0], %1, 0x989680;\n\t"
        "@P bra D_%=;\n\t"
        "bra W_%=;\n"
        "D_%=:\n\t}"
        :: "r"(mbar), "r"(parity) : "memory");
}
#define LDSM4(r0, r1, r2, r3, addr) \
    asm volatile("ldmatrix.sync.aligned.m8n8.x4.shared.b16 {%0,%1,%2,%3}, [%4];" \
                 : "=r"(r0), "=r"(r1), "=r"(r2), "=r"(r3) : "r"(addr))
__device__ __forceinline__ void mma_f16(float* c, const uint32_t* a, uint32_t b0, uint32_t b1) {
    asm volatile(
        "mma.sync.aligned.m16n8k16.row.col.f32.f16.f16.f32 "
        "{%0,%1,%2,%3}, {%4,%5,%6,%7}, {%8,%9}, {%0,%1,%2,%3};"
        : "+f"(c[0]), "+f"(c[1]), "+f"(c[2]), "+f"(c[3])
        : "r"(a[0]), "r"(a[1]), "r"(a[2]), "r"(a[3]), "r"(b0), "r"(b1));
}
__device__ __forceinline__ float sigmoidf_(float x) { return 1.f / (1.f + __expf(-x)); }

// ================= small kernels =================
__global__ void mean_kernel(const float* __restrict__ G, float* __restrict__ out) {
    const int bc = blockIdx.x;
    const float4* p = (const float4*)(G + (size_t)bc * HWSZ);
    float s = 0.f;
    for (int i = threadIdx.x; i < HWSZ / 4; i += blockDim.x) {
        float4 v = p[i];
        s += (v.x + v.y) + (v.z + v.w);
    }
    __shared__ float sm[256];
    sm[threadIdx.x] = s;
    __syncthreads();
    for (int k = 128; k > 0; k >>= 1) {
        if (threadIdx.x < k) sm[threadIdx.x] += sm[threadIdx.x + k];
        __syncthreads();
    }
    if (threadIdx.x == 0) out[bc] = sm[0] * (1.f / HWSZ);
}

__global__ void cvec_kernel(const float* __restrict__ Wout, const float* __restrict__ bout,
                            const float* __restrict__ gmean, float* __restrict__ cvec) {
    __shared__ float gm[CC];
    const int b = blockIdx.x, oc = threadIdx.x;
    gm[oc] = gmean[b * CC + oc];
    __syncthreads();
    float s = 0.f;
    #pragma unroll 8
    for (int c = 0; c < CC; ++c) s += Wout[(size_t)oc * CC + c] * gm[c];
    cvec[b * CC + oc] = 0.5f * s + bout[oc];
}

// fp32 weights [rows][256] -> padded fp16 [rows][KP] (pad zeroed)
__global__ void wconv(const float* __restrict__ W, __half* __restrict__ o) {
    const int row = blockIdx.x, k = threadIdx.x;
    o[(size_t)row * KP + k]       = __float2half(W[(size_t)row * 256 + k]);
    o[(size_t)row * KP + k + 128] = __float2half(W[(size_t)row * 256 + k + 128]);
    if (k < KP - 256) o[(size_t)row * KP + 256 + k] = __float2half(0.f);
}

// transpose fp32 X[b][C][HW] -> fp16 padded T[b][HW][KP]
__global__ void tconv(const float* __restrict__ X, __half* __restrict__ T) {
    __shared__ float t[32][33];
    const int b = blockIdx.z, k0 = blockIdx.y * 32, p0 = blockIdx.x * 32;
    const int tx = threadIdx.x, ty = threadIdx.y;
    const float* src = X + ((size_t)b * CC + k0) * HWSZ + p0;
    #pragma unroll
    for (int r = 0; r < 4; ++r)
        t[ty + r * 8][tx] = src[(size_t)(ty + r * 8) * HWSZ + tx];
    __syncthreads();
    #pragma unroll
    for (int r = 0; r < 4; ++r) {
        const int p = ty + r * 8;
        T[((size_t)b * HWSZ + p0 + p) * KP + k0 + tx] = __float2half(t[tx][p]);
    }
}

// psi-branch input: relu(V[pix]*wp1[c]+bp1[c]) -> fp16 padded [b][HW][KP]
__global__ void psix(const float* __restrict__ V, const float* __restrict__ wp1,
                     const float* __restrict__ bp1, __half* __restrict__ T) {
    const int b = blockIdx.y, tid = threadIdx.x;
    const float w = wp1[tid], bi = bp1[tid];
    const int p0 = blockIdx.x * 8;
    #pragma unroll
    for (int r = 0; r < 8; ++r) {
        float v = V[(size_t)b * HWSZ + p0 + r];
        T[((size_t)b * HWSZ + p0 + r) * KP + tid] = __float2half(fmaxf(v * w + bi, 0.f));
    }
}

// ================= bulk-copy HMMA GEMM =================
// D[m][n] = epi( sum_k A[m][k]*B[n][k] ), K=256 resident per row.
// A: resident, 128 rows (one bulk copy). B: streamed, 8 chunks x 32 rows, double-buffered.
// !SWAP: A=W (m=oc, 128), B=X (n=px, 256/block).  SWAP: A=X (m=px, 128), B=W (n=oc=256).
enum { EPI_QKV = 0, EPI_RELU_T = 1, EPI_SIG = 2, EPI_SIG_GATE = 3, EPI_OUT = 4 };

#define A_BYTES  (128 * KPB)        // 67584
#define XC_ROWS  32
#define XC_BYTES (XC_ROWS * KPB)    // 16896
#define SM_X0    A_BYTES
#define SM_X1    (A_BYTES + XC_BYTES)
#define MB_OFF   (A_BYTES + 2 * XC_BYTES)   // 101376
#define SMEM_TOTAL (MB_OFF + 32)

template<int EPI, bool SWAP>
__global__ void __launch_bounds__(256, 2)
gemm_bulk(const __half* __restrict__ A_, const __half* __restrict__ B_,
          const float* __restrict__ bias, const __half* __restrict__ gate,
          const float* __restrict__ cvec, float* __restrict__ Yf,
          __half* __restrict__ Yh, int OC)
{
    extern __shared__ char dsm[];
    const uint32_t smb = smem_u32(dsm);
    const int b = blockIdx.z;
    const int tid = threadIdx.x, wid = tid >> 5, lane = tid & 31;
    const int g = lane >> 2, t = lane & 3;
    const int warpM = wid & 3, warpN = wid >> 2;

    const size_t arow0 = SWAP ? ((size_t)b * HWSZ + (size_t)blockIdx.y * 128)
                              : (size_t)blockIdx.y * 128;
    const size_t brow0 = SWAP ? 0 : ((size_t)b * HWSZ + (size_t)blockIdx.x * 256);
    const __half* Ab = A_ + arow0 * KP;
    const __half* Bb = B_ + brow0 * KP;

    const uint32_t mbw = smb + MB_OFF, mbx0 = smb + MB_OFF + 8, mbx1 = smb + MB_OFF + 16;
    if (tid == 0) { mbar_init(mbw, 1); mbar_init(mbx0, 1); mbar_init(mbx1, 1); }
    __syncthreads();
    if (tid == 0) {
        expect_tx(mbw, A_BYTES);   bulk_g2s(smb,         Ab,                XC_ROWS ? A_BYTES : 0, mbw);
        expect_tx(mbx0, XC_BYTES); bulk_g2s(smb + SM_X0, Bb,                XC_BYTES, mbx0);
        expect_tx(mbx1, XC_BYTES); bulk_g2s(smb + SM_X1, Bb + XC_ROWS * KP, XC_BYTES, mbx1);
    }

    // ldmatrix addresses (528B row stride -> conflict-free)
    const int l7 = lane & 7;
    const uint32_t rowA0 = (uint32_t)(warpM * 32 + l7 + ((lane >> 3) & 1) * 8);
    const uint32_t aA0 = smb + rowA0 * KPB + ((lane >> 4) & 1) * 16;
    const uint32_t aA1 = aA0 + 16 * KPB;
    const uint32_t rowB0 = (uint32_t)(warpN * 16 + l7 + ((lane >> 4) & 1) * 8);
    const uint32_t bB0 = rowB0 * KPB + ((lane >> 3) & 1) * 16;   // relative to stage base
    mbar_wait(mbw, 0);
    int ph0 = 0, ph1 = 0;

    #pragma unroll 1
    for (int c = 0; c < 8; ++c) {
        const int s = c & 1;
        if (s == 0) { mbar_wait(mbx0, ph0); ph0 ^= 1; }
        else        { mbar_wait(mbx1, ph1); ph1 ^= 1; }
        const uint32_t xb = smb + SM_X0 + (uint32_t)s * XC_BYTES;

        float acc[2][2][4];
        #pragma unroll
        for (int mi = 0; mi < 2; ++mi)
            #pragma unroll
            for (int ni = 0; ni < 2; ++ni)
                #pragma unroll
                for (int u = 0; u < 4; ++u) acc[mi][ni][u] = 0.f;

        #pragma unroll
        for (int k16 = 0; k16 < 16; ++k16) {
            const uint32_t ko = (uint32_t)k16 * 32;
            uint32_t a0[4], a1[4], f0[4];
            LDSM4(a0[0], a0[1], a0[2], a0[3], aA0 + ko);
            LDSM4(a1[0], a1[1], a1[2], a1[3], aA1 + ko);
            LDSM4(f0[0], f0[1], f0[2], f0[3], xb + bB0 + ko);
            mma_f16(acc[0][0], a0, f0[0], f0[1]);
            mma_f16(acc[0][1], a0, f0[2], f0[3]);
            mma_f16(acc[1][0], a1, f0[0], f0[1]);
            mma_f16(acc[1][1], a1, f0[2], f0[3]);
        }
        __syncthreads();
        if (c + 2 < 8 && tid == 0) {
            const uint32_t mb = s ? mbx1 : mbx0;
            expect_tx(mb, XC_BYTES);
            bulk_g2s(smb + SM_X0 + (uint32_t)s * XC_BYTES,
                     Bb + (size_t)(c + 2) * XC_ROWS * KP, XC_BYTES, mb);
        }

        // ---- epilogue for this chunk (n range: c*32 + warpN*16 .. +16) ----
        const int nbase = c * 32 + warpN * 16;
        #pragma unroll
        for (int mi = 0; mi < 2; ++mi) {
            #pragma unroll
            for (int r2 = 0; r2 < 2; ++r2) {
                const int m = warpM * 32 + mi * 16 + g + r2 * 8;
                if (!SWAP) {
                    const int oc = (int)blockIdx.y * 128 + m;
                    float badd = 0.f, cv = 0.f;
                    if (EPI != EPI_OUT) badd = bias[oc];
                    if (EPI == EPI_OUT) cv = cvec[b * CC + oc];
                    const size_t ybase = ((size_t)b * OC + oc) * HWSZ + (size_t)blockIdx.x * 256;
                    #pragma unroll
                    for (int ni = 0; ni < 2; ++ni) {
                        const int n = nbase + ni * 8 + t * 2;
                        float v0 = acc[mi][ni][r2 * 2 + 0];
                        float v1 = acc[mi][ni][r2 * 2 + 1];
                        if (EPI == EPI_QKV) { v0 += badd; v1 += badd; }
                        else if (EPI == EPI_SIG) { v0 = sigmoidf_(v0 + badd); v1 = sigmoidf_(v1 + badd); }
                        else if (EPI == EPI_SIG_GATE) {
                            __half2 gg = *(const __half2*)(gate + ((size_t)b * CC + oc) * HWSZ
                                                           + (size_t)blockIdx.x * 256 + n);
                            v0 = sigmoidf_(v0 + badd) * (1.f - __half2float(gg.x));
                            v1 = sigmoidf_(v1 + badd) * (1.f - __half2float(gg.y));
                        } else if (EPI == EPI_OUT) { v0 = 0.5f * v0 + cv; v1 = 0.5f * v1 + cv; }
                        if (EPI == EPI_OUT) {
                            float2 r; r.x = v0; r.y = v1;
                            *(float2*)(Yf + ybase + n) = r;
                        } else {
                            __half2 r; r.x = __float2half(v0); r.y = __float2half(v1);
                            *(__half2*)(Yh + ybase + n) = r;
                        }
                    }
                } else {
                    // SWAP: m = pixel row, n = oc; relu + fp16 padded-transposed out
                    const size_t prow = (size_t)b * HWSZ + (size_t)blockIdx.y * 128 + m;
                    #pragma unroll
                    for (int ni = 0; ni < 2; ++ni) {
                        const int oc = nbase + ni * 8 + t * 2;
                        float v0 = fmaxf(acc[mi][ni][r2 * 2 + 0] + bias[oc], 0.f);
                        float v1 = fmaxf(acc[mi][ni][r2 * 2 + 1] + bias[oc + 1], 0.f);
                        __half2 r; r.x = __float2half(v0); r.y = __float2half(v1);
                        *(__half2*)(Yh + prow * KP + oc) = r;
                    }
                }
            }
        }
    }
}

// ================= windowed attention (fp16 in, fp16 padded-transposed out) =================
__global__ void __launch_bounds__(128)
attn_kernel(const __half* __restrict__ qkv, const __half* __restrict__ gk,
            const __half* __restrict__ gv, __half* __restrict__ ft)
{
    const int w = blockIdx.x, h = blockIdx.y;
    const int b = w >> 10, wy = (w >> 5) & 31, wx = w & 31;
    const int tid = threadIdx.x;

    __shared__ float Qs[49 * 33];
    __shared__ float Ks[49 * 33];
    __shared__ float Vs[49 * 33];
    __shared__ float S [49 * 49];

    const int row0 = wy * 7, col0 = wx * 7;

    for (int e = tid; e < 49 * 32; e += 128) {
        const int d = e / 49, n = e - d * 49;
        const int hw = (row0 + n / 7) * 224 + col0 + (n % 7);
        const int ch = h * 32 + d;
        const size_t qi = ((size_t)b * 768 + ch) * HWSZ + hw;
        const size_t gi = ((size_t)b * 256 + ch) * HWSZ + hw;
        Qs[n * 33 + d] = __half2float(qkv[qi]);
        Ks[n * 33 + d] = __half2float(qkv[qi + (size_t)256 * HWSZ]) * __half2float(gk[gi]);
        Vs[n * 33 + d] = __half2float(qkv[qi + (size_t)512 * HWSZ]) * __half2float(gv[gi]);
    }
    __syncthreads();

    const float scale = 0.17677669529663687f;
    for (int e = tid; e < 49 * 49; e += 128) {
        const int i = e / 49, j = e - i * 49;
        float s = 0.f;
        #pragma unroll
        for (int d = 0; d < 32; ++d) s += Qs[i * 33 + d] * Ks[j * 33 + d];
        S[e] = s * scale;
    }
    __syncthreads();

    if (tid < 49) {
        float m = -1e30f;
        for (int j = 0; j < 49; ++j) m = fmaxf(m, S[tid * 49 + j]);
        float sum = 0.f;
        for (int j = 0; j < 49; ++j) {
            float ev = __expf(S[tid * 49 + j] - m);
            S[tid * 49 + j] = ev;
            sum += ev;
        }
        const float inv = 1.f / sum;
        for (int j = 0; j < 49; ++j) S[tid * 49 + j] *= inv;
    }
    __syncthreads();

    for (int e = tid; e < 49 * 32; e += 128) {
        const int n = e >> 5, d = e & 31;
        float s = 0.f;
        #pragma unroll
        for (int m2 = 0; m2 < 49; ++m2) s += S[n * 49 + m2] * Vs[m2 * 33 + d];
        const int hw = (row0 + n / 7) * 224 + col0 + (n % 7);
        ft[((size_t)b * HWSZ + hw) * KP + h * 32 + d] = __float2half(s);
    }
}

// ================= launcher =================
extern "C" void kernel_launch(void* const* d_in, const int* in_sizes, int n_in,
                              void* d_out, int out_size) {
    (void)in_sizes; (void)n_in; (void)out_size;
    const float* G    = (const float*)d_in[0];
    const float* Vin  = (const float*)d_in[2];
    const float* Z    = (const float*)d_in[3];
    const float* Wqkv = (const float*)d_in[4];
    const float* bqkv = (const float*)d_in[5];
    const float* Wout = (const float*)d_in[6];
    const float* bout = (const float*)d_in[7];
    const float* Wk1  = (const float*)d_in[8];
    const float* bk1  = (const float*)d_in[9];
    const float* Wk2  = (const float*)d_in[10];
    const float* bk2  = (const float*)d_in[11];
    const float* Wv1  = (const float*)d_in[12];
    const float* bv1  = (const float*)d_in[13];
    const float* Wv2  = (const float*)d_in[14];
    const float* bv2  = (const float*)d_in[15];
    const float* Wp1  = (const float*)d_in[16];
    const float* bp1  = (const float*)d_in[17];
    const float* Wp2  = (const float*)d_in[18];
    const float* bp2  = (const float*)d_in[19];
    float* out = (float*)d_out;

    __half *qkv, *psi, *gk, *gv, *ta, *tb, *tc, *wp;
    float *gmean, *cvec;
    cudaGetSymbolAddress((void**)&qkv,   g_qkv);
    cudaGetSymbolAddress((void**)&psi,   g_psi);
    cudaGetSymbolAddress((void**)&gk,    g_gk);
    cudaGetSymbolAddress((void**)&gv,    g_gv);
    cudaGetSymbolAddress((void**)&gmean, g_mean);
    cudaGetSymbolAddress((void**)&cvec,  g_cvec);
    cudaGetSymbolAddress((void**)&ta,    g_ta);
    cudaGetSymbolAddress((void**)&tb,    g_tb);
    cudaGetSymbolAddress((void**)&tc,    g_tc);
    cudaGetSymbolAddress((void**)&wp,    g_wp);

    cudaFuncSetAttribute(gemm_bulk<EPI_QKV,      false>, cudaFuncAttributeMaxDynamicSharedMemorySize, SMEM_TOTAL);
    cudaFuncSetAttribute(gemm_bulk<EPI_RELU_T,   true>,  cudaFuncAttributeMaxDynamicSharedMemorySize, SMEM_TOTAL);
    cudaFuncSetAttribute(gemm_bulk<EPI_SIG,      false>, cudaFuncAttributeMaxDynamicSharedMemorySize, SMEM_TOTAL);
    cudaFuncSetAttribute(gemm_bulk<EPI_SIG_GATE, false>, cudaFuncAttributeMaxDynamicSharedMemorySize, SMEM_TOTAL);
    cudaFuncSetAttribute(gemm_bulk<EPI_OUT,      false>, cudaFuncAttributeMaxDynamicSharedMemorySize, SMEM_TOTAL);

    // weight row offsets (rows of KP)
    __half* wQKV = wp;
    __half* wK1  = wp + (size_t)768  * KP;
    __half* wK2  = wp + (size_t)1024 * KP;
    __half* wV1  = wp + (size_t)1280 * KP;
    __half* wV2  = wp + (size_t)1536 * KP;
    __half* wP2  = wp + (size_t)1792 * KP;
    __half* wOUT = wp + (size_t)2048 * KP;

    mean_kernel<<<1024, 256>>>(G, gmean);
    cvec_kernel<<<4, 256>>>(Wout, bout, gmean, cvec);

    wconv<<<768, 128>>>(Wqkv, wQKV);
    wconv<<<256, 128>>>(Wk1,  wK1);
    wconv<<<256, 128>>>(Wk2,  wK2);
    wconv<<<256, 128>>>(Wv1,  wV1);
    wconv<<<256, 128>>>(Wv2,  wV2);
    wconv<<<256, 128>>>(Wp2,  wP2);
    wconv<<<256, 128>>>(Wout, wOUT);

    const dim3 tgrid(HWSZ / 32, CC / 32, BB), tblk(32, 8);
    tconv<<<tgrid, tblk>>>(G, ta);
    tconv<<<tgrid, tblk>>>(Z, tb);
    psix<<<dim3(HWSZ / 8, BB), 256>>>(Vin, Wp1, bp1, tc);

    const dim3 gN(196, 2, BB);   // px-tiles(256) x oc-tiles(128) x B
    const dim3 gQ(196, 6, BB);
    const dim3 gS(1, 392, BB);   // SWAP: px-tiles(128) on y, all 256 oc streamed

    // psi = sigmoid(Wp2 @ relu(v*wp1+bp1) + bp2) -> fp16 [b][C][HW]
    gemm_bulk<EPI_SIG, false><<<gN, 256, SMEM_TOTAL>>>(
        wP2, tc, bp2, nullptr, nullptr, nullptr, psi, 256);

    // h = relu(Wk1@Z+bk1) -> fp16 padded [b][HW][KP]
    gemm_bulk<EPI_RELU_T, true><<<gS, 256, SMEM_TOTAL>>>(
        tb, wK1, bk1, nullptr, nullptr, nullptr, tc, 256);
    // gk = sigmoid(Wk2@h+bk2)*(1-psi)
    gemm_bulk<EPI_SIG_GATE, false><<<gN, 256, SMEM_TOTAL>>>(
        wK2, tc, bk2, psi, nullptr, nullptr, gk, 256);

    // gv likewise
    gemm_bulk<EPI_RELU_T, true><<<gS, 256, SMEM_TOTAL>>>(
        tb, wV1, bv1, nullptr, nullptr, nullptr, tc, 256);
    gemm_bulk<EPI_SIG_GATE, false><<<gN, 256, SMEM_TOTAL>>>(
        wV2, tc, bv2, psi, nullptr, nullptr, gv, 256);

    // qkv = Wqkv @ G + bqkv -> fp16 [b][768][HW]
    gemm_bulk<EPI_QKV, false><<<gQ, 256, SMEM_TOTAL>>>(
        wQKV, ta, bqkv, nullptr, nullptr, nullptr, qkv, 768);

    // attention -> fp16 padded f
    attn_kernel<<<dim3(4096, 8), 128>>>(qkv, gk, gv, tc);

    // out = 0.5 * Wout @ f + cvec -> fp32 d_out
    gemm_bulk<EPI_OUT, false><<<gN, 256, SMEM_TOTAL>>>(
        wOUT, tc, nullptr, nullptr, cvec, out, nullptr, 256);
}

// round 8
// speedup vs baseline: 3.2393x; 1.2110x over previous
#include <cuda_runtime.h>
#include <cuda_fp16.h>
#include <math.h>
#include <stdint.h>

#define HWSZ 50176           // 224*224
#define BB   4
#define CC   256
#define KP   264             // padded row stride (fp16): 528B = 33*16B
#define KPB  528

// ================= scratch (device globals) =================
__device__ __half g_qkv[(size_t)BB * 768 * HWSZ];   // [B][768][HW] fp16
__device__ __half g_psi[(size_t)BB * CC  * HWSZ];
__device__ __half g_gk [(size_t)BB * CC  * HWSZ];
__device__ __half g_gv [(size_t)BB * CC  * HWSZ];
__device__ float  g_mean[BB * CC];
__device__ float  g_cvec[BB * CC];
// fp16 transposed operands, padded rows [B][HW][KP]
__device__ __half g_ta[(size_t)BB * HWSZ * KP];
__device__ __half g_tb[(size_t)BB * HWSZ * KP];
__device__ __half g_tc[(size_t)BB * HWSZ * KP];
__device__ __half g_td[(size_t)BB * HWSZ * KP];
// padded fp16 weights: [qkv 768 | k1 256 | v1 256 | k2 | v2 | p2 | out] x KP
__device__ __half g_wp[2304 * KP];

// ================= PTX helpers =================
__device__ __forceinline__ uint32_t smem_u32(const void* p) {
    uint32_t a;
    asm("{ .reg .u64 t; cvta.to.shared.u64 t, %1; cvt.u32.u64 %0, t; }" : "=r"(a) : "l"(p));
    return a;
}
__device__ __forceinline__ void mbar_init(uint32_t a, uint32_t cnt) {
    asm volatile("mbarrier.init.shared.b64 [%0], %1;" :: "r"(a), "r"(cnt) : "memory");
}
__device__ __forceinline__ void expect_tx(uint32_t mbar, uint32_t bytes) {
    asm volatile("mbarrier.arrive.expect_tx.shared.b64 _, [%0], %1;" :: "r"(mbar), "r"(bytes) : "memory");
}
__device__ __forceinline__ void bulk_g2s(uint32_t dst, const void* src, uint32_t bytes, uint32_t mbar) {
    asm volatile("cp.async.bulk.shared::cluster.global.mbarrier::complete_tx::bytes [%0], [%1], %2, [%3];"
                 :: "r"(dst), "l"(src), "r"(bytes), "r"(mbar) : "memory");
}
__device__ __forceinline__ void mbar_wait(uint32_t mbar, uint32_t parity) {
    asm volatile(
        "{\n\t.reg .pred P;\n"
        "W_%=:\n\t"
        "mbarrier.try_wait.parity.acquire.cta.shared::cta.b64 P, [%0], %1, 0x989680;\n\t"
        "@P bra D_%=;\n\t"
        "bra W_%=;\n"
        "D_%=:\n\t}"
        :: "r"(mbar), "r"(parity) : "memory");
}
#define LDSM4(r0, r1, r2, r3, addr) \
    asm volatile("ldmatrix.sync.aligned.m8n8.x4.shared.b16 {%0,%1,%2,%3}, [%4];" \
                 : "=r"(r0), "=r"(r1), "=r"(r2), "=r"(r3) : "r"(addr))
__device__ __forceinline__ void mma_f16(float* c, const uint32_t* a, uint32_t b0, uint32_t b1) {
    asm volatile(
        "mma.sync.aligned.m16n8k16.row.col.f32.f16.f16.f32 "
        "{%0,%1,%2,%3}, {%4,%5,%6,%7}, {%8,%9}, {%0,%1,%2,%3};"
        : "+f"(c[0]), "+f"(c[1]), "+f"(c[2]), "+f"(c[3])
        : "r"(a[0]), "r"(a[1]), "r"(a[2]), "r"(a[3]), "r"(b0), "r"(b1));
}
__device__ __forceinline__ float sigmoidf_(float x) { return 1.f / (1.f + __expf(-x)); }

// ================= small kernels =================
__global__ void mean_kernel(const float* __restrict__ G, float* __restrict__ out) {
    const int bc = blockIdx.x;
    const float4* p = (const float4*)(G + (size_t)bc * HWSZ);
    float s = 0.f;
    for (int i = threadIdx.x; i < HWSZ / 4; i += blockDim.x) {
        float4 v = p[i];
        s += (v.x + v.y) + (v.z + v.w);
    }
    __shared__ float sm[256];
    sm[threadIdx.x] = s;
    __syncthreads();
    for (int k = 128; k > 0; k >>= 1) {
        if (threadIdx.x < k) sm[threadIdx.x] += sm[threadIdx.x + k];
        __syncthreads();
    }
    if (threadIdx.x == 0) out[bc] = sm[0] * (1.f / HWSZ);
}

__global__ void cvec_kernel(const float* __restrict__ Wout, const float* __restrict__ bout,
                            const float* __restrict__ gmean, float* __restrict__ cvec) {
    __shared__ float gm[CC];
    const int b = blockIdx.x, oc = threadIdx.x;
    gm[oc] = gmean[b * CC + oc];
    __syncthreads();
    float s = 0.f;
    #pragma unroll 8
    for (int c = 0; c < CC; ++c) s += Wout[(size_t)oc * CC + c] * gm[c];
    cvec[b * CC + oc] = 0.5f * s + bout[oc];
}

// fp32 weights [rows][256] -> padded fp16 [rows][KP] (pad zeroed)
__global__ void wconv(const float* __restrict__ W, __half* __restrict__ o) {
    const int row = blockIdx.x, k = threadIdx.x;
    o[(size_t)row * KP + k]       = __float2half(W[(size_t)row * 256 + k]);
    o[(size_t)row * KP + k + 128] = __float2half(W[(size_t)row * 256 + k + 128]);
    if (k < KP - 256) o[(size_t)row * KP + 256 + k] = __float2half(0.f);
}

// transpose fp32 X[b][C][HW] -> fp16 padded T[b][HW][KP]
__global__ void tconv(const float* __restrict__ X, __half* __restrict__ T) {
    __shared__ float t[32][33];
    const int b = blockIdx.z, k0 = blockIdx.y * 32, p0 = blockIdx.x * 32;
    const int tx = threadIdx.x, ty = threadIdx.y;
    const float* src = X + ((size_t)b * CC + k0) * HWSZ + p0;
    #pragma unroll
    for (int r = 0; r < 4; ++r)
        t[ty + r * 8][tx] = src[(size_t)(ty + r * 8) * HWSZ + tx];
    __syncthreads();
    #pragma unroll
    for (int r = 0; r < 4; ++r) {
        const int p = ty + r * 8;
        T[((size_t)b * HWSZ + p0 + p) * KP + k0 + tx] = __float2half(t[tx][p]);
    }
}

// psi-branch input: relu(V[pix]*wp1[c]+bp1[c]) -> fp16 padded [b][HW][KP]
__global__ void psix(const float* __restrict__ V, const float* __restrict__ wp1,
                     const float* __restrict__ bp1, __half* __restrict__ T) {
    const int b = blockIdx.y, tid = threadIdx.x;
    const float w = wp1[tid], bi = bp1[tid];
    const int p0 = blockIdx.x * 8;
    #pragma unroll
    for (int r = 0; r < 8; ++r) {
        float v = V[(size_t)b * HWSZ + p0 + r];
        T[((size_t)b * HWSZ + p0 + r) * KP + tid] = __float2half(fmaxf(v * w + bi, 0.f));
    }
}

// ================= bulk-copy HMMA GEMM =================
enum { EPI_QKV = 0, EPI_RELU_T = 1, EPI_SIG = 2, EPI_SIG_GATE = 3, EPI_OUT = 4 };

#define A_BYTES  (128 * KPB)        // 67584
#define XC_ROWS  32
#define XC_BYTES (XC_ROWS * KPB)    // 16896
#define SM_X0    A_BYTES
#define SM_X1    (A_BYTES + XC_BYTES)
#define MB_OFF   (A_BYTES + 2 * XC_BYTES)
#define SMEM_TOTAL (MB_OFF + 32)

// !SWAP: A=W (m=oc, 128 resident), B=X (n=px, NCH*32 streamed).
//  SWAP: A=X (m=px, 128 resident), B=W (n=oc, NCH*32 streamed); dual output (k1/v1 fused).
template<int EPI, bool SWAP, int NCH>
__global__ void __launch_bounds__(256, 2)
gemm_bulk(const __half* __restrict__ A_, const __half* __restrict__ B_,
          const float* __restrict__ bias, const __half* __restrict__ gate,
          const float* __restrict__ cvec, float* __restrict__ Yf,
          __half* __restrict__ Yh, int OC,
          const float* __restrict__ bias2, __half* __restrict__ Yh2)
{
    extern __shared__ char dsm[];
    const uint32_t smb = smem_u32(dsm);
    const int b = blockIdx.z;
    const int tid = threadIdx.x, wid = tid >> 5, lane = tid & 31;
    const int g = lane >> 2, t = lane & 3;
    const int warpM = wid & 3, warpN = wid >> 2;

    const size_t arow0 = SWAP ? ((size_t)b * HWSZ + (size_t)blockIdx.y * 128)
                              : (size_t)blockIdx.y * 128;
    const size_t brow0 = SWAP ? 0 : ((size_t)b * HWSZ + (size_t)blockIdx.x * (NCH * 32));
    const __half* Ab = A_ + arow0 * KP;
    const __half* Bb = B_ + brow0 * KP;

    const uint32_t mbw = smb + MB_OFF, mbx0 = smb + MB_OFF + 8, mbx1 = smb + MB_OFF + 16;
    if (tid == 0) { mbar_init(mbw, 1); mbar_init(mbx0, 1); mbar_init(mbx1, 1); }
    __syncthreads();
    if (tid == 0) {
        expect_tx(mbw, A_BYTES);   bulk_g2s(smb,         Ab,                A_BYTES,  mbw);
        expect_tx(mbx0, XC_BYTES); bulk_g2s(smb + SM_X0, Bb,                XC_BYTES, mbx0);
        expect_tx(mbx1, XC_BYTES); bulk_g2s(smb + SM_X1, Bb + XC_ROWS * KP, XC_BYTES, mbx1);
    }

    // ldmatrix addresses (528B row stride -> conflict-free)
    const int l7 = lane & 7;
    const uint32_t rowA0 = (uint32_t)(warpM * 32 + l7 + ((lane >> 3) & 1) * 8);
    const uint32_t aA0 = smb + rowA0 * KPB + ((lane >> 4) & 1) * 16;
    const uint32_t aA1 = aA0 + 16 * KPB;
    const uint32_t rowB0 = (uint32_t)(warpN * 16 + l7 + ((lane >> 4) & 1) * 8);
    const uint32_t bB0 = rowB0 * KPB + ((lane >> 3) & 1) * 16;
    mbar_wait(mbw, 0);
    int ph0 = 0, ph1 = 0;

    #pragma unroll 1
    for (int c = 0; c < NCH; ++c) {
        const int s = c & 1;
        if (s == 0) { mbar_wait(mbx0, ph0); ph0 ^= 1; }
        else        { mbar_wait(mbx1, ph1); ph1 ^= 1; }
        const uint32_t xb = smb + SM_X0 + (uint32_t)s * XC_BYTES;

        float acc[2][2][4];
        #pragma unroll
        for (int mi = 0; mi < 2; ++mi)
            #pragma unroll
            for (int ni = 0; ni < 2; ++ni)
                #pragma unroll
                for (int u = 0; u < 4; ++u) acc[mi][ni][u] = 0.f;

        #pragma unroll
        for (int k16 = 0; k16 < 16; ++k16) {
            const uint32_t ko = (uint32_t)k16 * 32;
            uint32_t a0[4], a1[4], f0[4];
            LDSM4(a0[0], a0[1], a0[2], a0[3], aA0 + ko);
            LDSM4(a1[0], a1[1], a1[2], a1[3], aA1 + ko);
            LDSM4(f0[0], f0[1], f0[2], f0[3], xb + bB0 + ko);
            mma_f16(acc[0][0], a0, f0[0], f0[1]);
            mma_f16(acc[0][1], a0, f0[2], f0[3]);
            mma_f16(acc[1][0], a1, f0[0], f0[1]);
            mma_f16(acc[1][1], a1, f0[2], f0[3]);
        }
        __syncthreads();
        if (c + 2 < NCH && tid == 0) {
            const uint32_t mb = s ? mbx1 : mbx0;
            expect_tx(mb, XC_BYTES);
            bulk_g2s(smb + SM_X0 + (uint32_t)s * XC_BYTES,
                     Bb + (size_t)(c + 2) * XC_ROWS * KP, XC_BYTES, mb);
        }

        const int nbase = c * 32 + warpN * 16;
        #pragma unroll
        for (int mi = 0; mi < 2; ++mi) {
            #pragma unroll
            for (int r2 = 0; r2 < 2; ++r2) {
                const int m = warpM * 32 + mi * 16 + g + r2 * 8;
                if (!SWAP) {
                    const int oc = (int)blockIdx.y * 128 + m;
                    float badd = 0.f, cv = 0.f;
                    if (EPI != EPI_OUT) badd = bias[oc];
                    if (EPI == EPI_OUT) cv = cvec[b * CC + oc];
                    const size_t ybase = ((size_t)b * OC + oc) * HWSZ + (size_t)blockIdx.x * (NCH * 32);
                    #pragma unroll
                    for (int ni = 0; ni < 2; ++ni) {
                        const int n = nbase + ni * 8 + t * 2;
                        float v0 = acc[mi][ni][r2 * 2 + 0];
                        float v1 = acc[mi][ni][r2 * 2 + 1];
                        if (EPI == EPI_QKV) { v0 += badd; v1 += badd; }
                        else if (EPI == EPI_SIG) { v0 = sigmoidf_(v0 + badd); v1 = sigmoidf_(v1 + badd); }
                        else if (EPI == EPI_SIG_GATE) {
                            __half2 gg = *(const __half2*)(gate + ((size_t)b * CC + oc) * HWSZ
                                                           + (size_t)blockIdx.x * (NCH * 32) + n);
                            v0 = sigmoidf_(v0 + badd) * (1.f - __half2float(gg.x));
                            v1 = sigmoidf_(v1 + badd) * (1.f - __half2float(gg.y));
                        } else if (EPI == EPI_OUT) { v0 = 0.5f * v0 + cv; v1 = 0.5f * v1 + cv; }
                        if (EPI == EPI_OUT) {
                            float2 r; r.x = v0; r.y = v1;
                            *(float2*)(Yf + ybase + n) = r;
                        } else {
                            __half2 r; r.x = __float2half(v0); r.y = __float2half(v1);
                            *(__half2*)(Yh + ybase + n) = r;
                        }
                    }
                } else {
                    // SWAP dual: m = pixel row, n = oc in [0, NCH*32); split at 256
                    const size_t prow = (size_t)b * HWSZ + (size_t)blockIdx.y * 128 + m;
                    #pragma unroll
                    for (int ni = 0; ni < 2; ++ni) {
                        const int oc = nbase + ni * 8 + t * 2;
                        const float* bp = bias;
                        __half* yp = Yh;
                        int o2 = oc;
                        if (oc >= 256) { bp = bias2; yp = Yh2; o2 = oc - 256; }
                        float v0 = fmaxf(acc[mi][ni][r2 * 2 + 0] + bp[o2], 0.f);
                        float v1 = fmaxf(acc[mi][ni][r2 * 2 + 1] + bp[o2 + 1], 0.f);
                        __half2 r; r.x = __float2half(v0); r.y = __float2half(v1);
                        *(__half2*)(yp + prow * KP + o2) = r;
                    }
                }
            }
        }
    }
}

// ================= windowed attention (register-tiled SIMT) =================
__global__ void __launch_bounds__(128)
attn_kernel(const __half* __restrict__ qkv, const __half* __restrict__ gk,
            const __half* __restrict__ gv, __half* __restrict__ ft)
{
    const int w = blockIdx.x, h = blockIdx.y;
    const int b = w >> 10, wy = (w >> 5) & 31, wx = w & 31;
    const int tid = threadIdx.x;

    __shared__ float Qs[49 * 33];
    __shared__ float Ks[49 * 33];
    __shared__ float Vs[49 * 33];
    __shared__ float S [49 * 49];

    const int row0 = wy * 7, col0 = wx * 7;

    for (int e = tid; e < 49 * 32; e += 128) {
        const int d = e / 49, n = e - d * 49;
        const int hw = (row0 + n / 7) * 224 + col0 + (n % 7);
        const int ch = h * 32 + d;
        const size_t qi = ((size_t)b * 768 + ch) * HWSZ + hw;
        const size_t gi = ((size_t)b * 256 + ch) * HWSZ + hw;
        Qs[n * 33 + d] = __half2float(qkv[qi]);
        Ks[n * 33 + d] = __half2float(qkv[qi + (size_t)256 * HWSZ]) * __half2float(gk[gi]);
        Vs[n * 33 + d] = __half2float(qkv[qi + (size_t)512 * HWSZ]) * __half2float(gv[gi]);
    }
    __syncthreads();

    const float scale = 0.17677669529663687f;   // 32^-0.5

    // ---- QK^T: 7x4 register tiles, 91 threads ----
    if (tid < 91) {
        const int i0 = (tid / 13) * 7;
        const int j0 = (tid % 13) * 4;
        float acc[7][4];
        #pragma unroll
        for (int r = 0; r < 7; ++r)
            #pragma unroll
            for (int c2 = 0; c2 < 4; ++c2) acc[r][c2] = 0.f;
        int jc[4];
        #pragma unroll
        for (int c2 = 0; c2 < 4; ++c2) jc[c2] = min(j0 + c2, 48);
        #pragma unroll
        for (int d = 0; d < 32; ++d) {
            float kv[4];
            #pragma unroll
            for (int c2 = 0; c2 < 4; ++c2) kv[c2] = Ks[jc[c2] * 33 + d];
            #pragma unroll
            for (int r = 0; r < 7; ++r) {
                const float qv = Qs[(i0 + r) * 33 + d];
                #pragma unroll
                for (int c2 = 0; c2 < 4; ++c2) acc[r][c2] += qv * kv[c2];
            }
        }
        #pragma unroll
        for (int r = 0; r < 7; ++r)
            #pragma unroll
            for (int c2 = 0; c2 < 4; ++c2)
                if (j0 + c2 < 49) S[(i0 + r) * 49 + j0 + c2] = acc[r][c2] * scale;
    }
    __syncthreads();

    // ---- softmax: one row per thread ----
    if (tid < 49) {
        float m = -1e30f;
        for (int j = 0; j < 49; ++j) m = fmaxf(m, S[tid * 49 + j]);
        float sum = 0.f;
        for (int j = 0; j < 49; ++j) {
            float ev = __expf(S[tid * 49 + j] - m);
            S[tid * 49 + j] = ev;
            sum += ev;
        }
        const float inv = 1.f / sum;
        for (int j = 0; j < 49; ++j) S[tid * 49 + j] *= inv;
    }
    __syncthreads();

    // ---- S @ V: 4x4 register tiles, 104 threads ----
    if (tid < 104) {
        const int n0 = (tid / 8) * 4;
        const int d0 = (tid & 7) * 4;
        float acc[4][4];
        #pragma unroll
        for (int r = 0; r < 4; ++r)
            #pragma unroll
            for (int c2 = 0; c2 < 4; ++c2) acc[r][c2] = 0.f;
        int nr[4];
        #pragma unroll
        for (int r = 0; r < 4; ++r) nr[r] = min(n0 + r, 48);
        #pragma unroll 7
        for (int m2 = 0; m2 < 49; ++m2) {
            float vv[4];
            #pragma unroll
            for (int c2 = 0; c2 < 4; ++c2) vv[c2] = Vs[m2 * 33 + d0 + c2];
            #pragma unroll
            for (int r = 0; r < 4; ++r) {
                const float sv = S[nr[r] * 49 + m2];
                #pragma unroll
                for (int c2 = 0; c2 < 4; ++c2) acc[r][c2] += sv * vv[c2];
            }
        }
        #pragma unroll
        for (int r = 0; r < 4; ++r) {
            const int n = n0 + r;
            if (n < 49) {
                const int hw = (row0 + n / 7) * 224 + col0 + (n % 7);
                #pragma unroll
                for (int c2 = 0; c2 < 4; ++c2)
                    ft[((size_t)b * HWSZ + hw) * KP + h * 32 + d0 + c2] = __float2half(acc[r][c2]);
            }
        }
    }
}

// ================= launcher =================
extern "C" void kernel_launch(void* const* d_in, const int* in_sizes, int n_in,
                              void* d_out, int out_size) {
    (void)in_sizes; (void)n_in; (void)out_size;
    const float* G    = (const float*)d_in[0];
    const float* Vin  = (const float*)d_in[2];
    const float* Z    = (const float*)d_in[3];
    const float* Wqkv = (const float*)d_in[4];
    const float* bqkv = (const float*)d_in[5];
    const float* Wout = (const float*)d_in[6];
    const float* bout = (const float*)d_in[7];
    const float* Wk1  = (const float*)d_in[8];
    const float* bk1  = (const float*)d_in[9];
    const float* Wk2  = (const float*)d_in[10];
    const float* bk2  = (const float*)d_in[11];
    const float* Wv1  = (const float*)d_in[12];
    const float* bv1  = (const float*)d_in[13];
    const float* Wv2  = (const float*)d_in[14];
    const float* bv2  = (const float*)d_in[15];
    const float* Wp1  = (const float*)d_in[16];
    const float* bp1  = (const float*)d_in[17];
    const float* Wp2  = (const float*)d_in[18];
    const float* bp2  = (const float*)d_in[19];
    float* out = (float*)d_out;

    __half *qkv, *psi, *gk, *gv, *ta, *tb, *tc, *td, *wp;
    float *gmean, *cvec;
    cudaGetSymbolAddress((void**)&qkv,   g_qkv);
    cudaGetSymbolAddress((void**)&psi,   g_psi);
    cudaGetSymbolAddress((void**)&gk,    g_gk);
    cudaGetSymbolAddress((void**)&gv,    g_gv);
    cudaGetSymbolAddress((void**)&gmean, g_mean);
    cudaGetSymbolAddress((void**)&cvec,  g_cvec);
    cudaGetSymbolAddress((void**)&ta,    g_ta);
    cudaGetSymbolAddress((void**)&tb,    g_tb);
    cudaGetSymbolAddress((void**)&tc,    g_tc);
    cudaGetSymbolAddress((void**)&td,    g_td);
    cudaGetSymbolAddress((void**)&wp,    g_wp);

    cudaFuncSetAttribute(gemm_bulk<EPI_QKV,      false, 8>,  cudaFuncAttributeMaxDynamicSharedMemorySize, SMEM_TOTAL);
    cudaFuncSetAttribute(gemm_bulk<EPI_RELU_T,   true,  16>, cudaFuncAttributeMaxDynamicSharedMemorySize, SMEM_TOTAL);
    cudaFuncSetAttribute(gemm_bulk<EPI_SIG,      false, 8>,  cudaFuncAttributeMaxDynamicSharedMemorySize, SMEM_TOTAL);
    cudaFuncSetAttribute(gemm_bulk<EPI_SIG_GATE, false, 8>,  cudaFuncAttributeMaxDynamicSharedMemorySize, SMEM_TOTAL);
    cudaFuncSetAttribute(gemm_bulk<EPI_OUT,      false, 8>,  cudaFuncAttributeMaxDynamicSharedMemorySize, SMEM_TOTAL);

    // weight layout (rows of KP)
    __half* wQKV = wp;
    __half* wKV1 = wp + (size_t)768  * KP;   // k1 rows [0,256), v1 rows [256,512)
    __half* wK2  = wp + (size_t)1280 * KP;
    __half* wV2  = wp + (size_t)1536 * KP;
    __half* wP2  = wp + (size_t)1792 * KP;
    __half* wOUT = wp + (size_t)2048 * KP;

    const dim3 tgrid(HWSZ / 32, CC / 32, BB), tblk(32, 8);
    const dim3 gN(196, 2, BB);    // px-tiles(256) x oc-tiles(128) x B
    const dim3 gQ(196, 6, BB);
    const dim3 gS(1, 392, BB);    // SWAP: px-tiles(128), 512 oc streamed

    // --- ordered so launch index 5 is the qkv GEMM (ncu -s 5 -c 1) ---
    mean_kernel<<<1024, 256>>>(G, gmean);                       // 0
    cvec_kernel<<<4, 256>>>(Wout, bout, gmean, cvec);           // 1
    wconv<<<768, 128>>>(Wqkv, wQKV);                            // 2
    tconv<<<tgrid, tblk>>>(G, ta);                              // 3
    tconv<<<tgrid, tblk>>>(Z, tb);                              // 4
    gemm_bulk<EPI_QKV, false, 8><<<gQ, 256, SMEM_TOTAL>>>(      // 5  <-- profiled
        wQKV, ta, bqkv, nullptr, nullptr, nullptr, qkv, 768, nullptr, nullptr);

    wconv<<<256, 128>>>(Wk1,  wKV1);
    wconv<<<256, 128>>>(Wv1,  wKV1 + (size_t)256 * KP);
    wconv<<<256, 128>>>(Wk2,  wK2);
    wconv<<<256, 128>>>(Wv2,  wV2);
    wconv<<<256, 128>>>(Wp2,  wP2);
    wconv<<<256, 128>>>(Wout, wOUT);
    psix<<<dim3(HWSZ / 8, BB), 256>>>(Vin, Wp1, bp1, tc);

    // psi = sigmoid(Wp2 @ relu(v*wp1+bp1) + bp2) -> fp16 [b][C][HW]
    gemm_bulk<EPI_SIG, false, 8><<<gN, 256, SMEM_TOTAL>>>(
        wP2, tc, bp2, nullptr, nullptr, nullptr, psi, 256, nullptr, nullptr);

    // fused h_k / h_v = relu(W{k1,v1}@Z + b) -> tc, td (padded transposed fp16)
    gemm_bulk<EPI_RELU_T, true, 16><<<gS, 256, SMEM_TOTAL>>>(
        tb, wKV1, bk1, nullptr, nullptr, nullptr, tc, 512, bv1, td);

    // gk = sigmoid(Wk2@h_k+bk2)*(1-psi);  gv likewise from h_v
    gemm_bulk<EPI_SIG_GATE, false, 8><<<gN, 256, SMEM_TOTAL>>>(
        wK2, tc, bk2, psi, nullptr, nullptr, gk, 256, nullptr, nullptr);
    gemm_bulk<EPI_SIG_GATE, false, 8><<<gN, 256, SMEM_TOTAL>>>(
        wV2, td, bv2, psi, nullptr, nullptr, gv, 256, nullptr, nullptr);

    // attention -> fp16 padded f (reuses tc)
    attn_kernel<<<dim3(4096, 8), 128>>>(qkv, gk, gv, tc);

    // out = 0.5 * Wout @ f + cvec -> fp32 d_out
    gemm_bulk<EPI_OUT, false, 8><<<gN, 256, SMEM_TOTAL>>>(
        wOUT, tc, nullptr, nullptr, cvec, out, nullptr, 256, nullptr, nullptr);
}

// round 9
// speedup vs baseline: 3.6316x; 1.1211x over previous
#include <cuda_runtime.h>
#include <cuda_fp16.h>
#include <math.h>
#include <stdint.h>

#define HWSZ 50176           // 224*224
#define BB   4
#define CC   256
#define KP   264             // padded row stride (fp16): 528B = 33*16B
#define KPB  528

// ================= scratch (device globals) =================
__device__ __half g_qkv[(size_t)BB * HWSZ * 768];   // pixel-major [B][HW][768]
__device__ __half g_psi[(size_t)BB * HWSZ * CC];    // [B][HW][256]
__device__ __half g_gk [(size_t)BB * HWSZ * CC];
__device__ __half g_gv [(size_t)BB * HWSZ * CC];
__device__ float  g_mean[BB * CC];
__device__ float  g_cvec[BB * CC];
// fp16 padded operands [B][HW][KP]
__device__ __half g_ta[(size_t)BB * HWSZ * KP];
__device__ __half g_tb[(size_t)BB * HWSZ * KP];
__device__ __half g_tc[(size_t)BB * HWSZ * KP];
__device__ __half g_td[(size_t)BB * HWSZ * KP];
// padded fp16 weights: [qkv 768 | k1 256 | v1 256 | k2 | v2 | p2 | out] x KP
__device__ __half g_wp[2304 * KP];

// ================= PTX helpers =================
__device__ __forceinline__ uint32_t smem_u32(const void* p) {
    uint32_t a;
    asm("{ .reg .u64 t; cvta.to.shared.u64 t, %1; cvt.u32.u64 %0, t; }" : "=r"(a) : "l"(p));
    return a;
}
__device__ __forceinline__ void mbar_init(uint32_t a, uint32_t cnt) {
    asm volatile("mbarrier.init.shared.b64 [%0], %1;" :: "r"(a), "r"(cnt) : "memory");
}
__device__ __forceinline__ void expect_tx(uint32_t mbar, uint32_t bytes) {
    asm volatile("mbarrier.arrive.expect_tx.shared.b64 _, [%0], %1;" :: "r"(mbar), "r"(bytes) : "memory");
}
__device__ __forceinline__ void bulk_g2s(uint32_t dst, const void* src, uint32_t bytes, uint32_t mbar) {
    asm volatile("cp.async.bulk.shared::cluster.global.mbarrier::complete_tx::bytes [%0], [%1], %2, [%3];"
                 :: "r"(dst), "l"(src), "r"(bytes), "r"(mbar) : "memory");
}
__device__ __forceinline__ void mbar_wait(uint32_t mbar, uint32_t parity) {
    asm volatile(
        "{\n\t.reg .pred P;\n"
        "W_%=:\n\t"
        "mbarrier.try_wait.parity.acquire.cta.shared::cta.b64 P, [%0], %1, 0x989680;\n\t"
        "@P bra D_%=;\n\t"
        "bra W_%=;\n"
        "D_%=:\n\t}"
        :: "r"(mbar), "r"(parity) : "memory");
}
#define LDSM4(r0, r1, r2, r3, addr) \
    asm volatile("ldmatrix.sync.aligned.m8n8.x4.shared.b16 {%0,%1,%2,%3}, [%4];" \
                 : "=r"(r0), "=r"(r1), "=r"(r2), "=r"(r3) : "r"(addr))
__device__ __forceinline__ void mma_f16(float* c, const uint32_t* a, uint32_t b0, uint32_t b1) {
    asm volatile(
        "mma.sync.aligned.m16n8k16.row.col.f32.f16.f16.f32 "
        "{%0,%1,%2,%3}, {%4,%5,%6,%7}, {%8,%9}, {%0,%1,%2,%3};"
        : "+f"(c[0]), "+f"(c[1]), "+f"(c[2]), "+f"(c[3])
        : "r"(a[0]), "r"(a[1]), "r"(a[2]), "r"(a[3]), "r"(b0), "r"(b1));
}
__device__ __forceinline__ float sigmoidf_(float x) { return 1.f / (1.f + __expf(-x)); }

// ================= small kernels =================
__global__ void mean_kernel(const float* __restrict__ G, float* __restrict__ out) {
    const int bc = blockIdx.x;
    const float4* p = (const float4*)(G + (size_t)bc * HWSZ);
    float s = 0.f;
    for (int i = threadIdx.x; i < HWSZ / 4; i += blockDim.x) {
        float4 v = p[i];
        s += (v.x + v.y) + (v.z + v.w);
    }
    __shared__ float sm[256];
    sm[threadIdx.x] = s;
    __syncthreads();
    for (int k = 128; k > 0; k >>= 1) {
        if (threadIdx.x < k) sm[threadIdx.x] += sm[threadIdx.x + k];
        __syncthreads();
    }
    if (threadIdx.x == 0) out[bc] = sm[0] * (1.f / HWSZ);
}

__global__ void cvec_kernel(const float* __restrict__ Wout, const float* __restrict__ bout,
                            const float* __restrict__ gmean, float* __restrict__ cvec) {
    __shared__ float gm[CC];
    const int b = blockIdx.x, oc = threadIdx.x;
    gm[oc] = gmean[b * CC + oc];
    __syncthreads();
    float s = 0.f;
    #pragma unroll 8
    for (int c = 0; c < CC; ++c) s += Wout[(size_t)oc * CC + c] * gm[c];
    cvec[b * CC + oc] = 0.5f * s + bout[oc];
}

// fp32 weights [rows][256] -> padded fp16 [rows][KP] (pad zeroed)
__global__ void wconv(const float* __restrict__ W, __half* __restrict__ o) {
    const int row = blockIdx.x, k = threadIdx.x;
    o[(size_t)row * KP + k]       = __float2half(W[(size_t)row * 256 + k]);
    o[(size_t)row * KP + k + 128] = __float2half(W[(size_t)row * 256 + k + 128]);
    if (k < KP - 256) o[(size_t)row * KP + 256 + k] = __float2half(0.f);
}

// transpose fp32 X[b][C][HW] -> fp16 padded T[b][HW][KP]
__global__ void tconv(const float* __restrict__ X, __half* __restrict__ T) {
    __shared__ float t[32][33];
    const int b = blockIdx.z, k0 = blockIdx.y * 32, p0 = blockIdx.x * 32;
    const int tx = threadIdx.x, ty = threadIdx.y;
    const float* src = X + ((size_t)b * CC + k0) * HWSZ + p0;
    #pragma unroll
    for (int r = 0; r < 4; ++r)
        t[ty + r * 8][tx] = src[(size_t)(ty + r * 8) * HWSZ + tx];
    __syncthreads();
    #pragma unroll
    for (int r = 0; r < 4; ++r) {
        const int p = ty + r * 8;
        T[((size_t)b * HWSZ + p0 + p) * KP + k0 + tx] = __float2half(t[tx][p]);
    }
}

// psi-branch input: relu(V[pix]*wp1[c]+bp1[c]) -> fp16 padded [b][HW][KP]
__global__ void psix(const float* __restrict__ V, const float* __restrict__ wp1,
                     const float* __restrict__ bp1, __half* __restrict__ T) {
    const int b = blockIdx.y, tid = threadIdx.x;
    const float w = wp1[tid], bi = bp1[tid];
    const int p0 = blockIdx.x * 8;
    #pragma unroll
    for (int r = 0; r < 8; ++r) {
        float v = V[(size_t)b * HWSZ + p0 + r];
        T[((size_t)b * HWSZ + p0 + r) * KP + tid] = __float2half(fmaxf(v * w + bi, 0.f));
    }
}

// ================= bulk-copy HMMA GEMM =================
// SWAP modes (pixel-major outputs): A = X pixels (128 resident), B = weights streamed (NCH*32 oc).
// !SWAP (EPI_OUT only): A = W (128 oc resident), B = f pixels streamed.
enum { EPI_QKV_T = 0, EPI_RELU_T = 1, EPI_SIG_T = 2, EPI_SIG_GATE_T = 3, EPI_OUT = 4 };

#define A_BYTES  (128 * KPB)        // 67584
#define XC_ROWS  32
#define XC_BYTES (XC_ROWS * KPB)    // 16896
#define SM_X0    A_BYTES
#define SM_X1    (A_BYTES + XC_BYTES)
#define MB_OFF   (A_BYTES + 2 * XC_BYTES)
#define SMEM_TOTAL (MB_OFF + 32)

template<int EPI, bool SWAP, int NCH>
__global__ void __launch_bounds__(256, 2)
gemm_bulk(const __half* __restrict__ A_, const __half* __restrict__ B_,
          const float* __restrict__ bias, const __half* __restrict__ gate,
          const float* __restrict__ cvec, float* __restrict__ Yf,
          __half* __restrict__ Yh, int OS,
          const float* __restrict__ bias2, __half* __restrict__ Yh2)
{
    extern __shared__ char dsm[];
    const uint32_t smb = smem_u32(dsm);
    const int b = blockIdx.z;
    const int tid = threadIdx.x, wid = tid >> 5, lane = tid & 31;
    const int g = lane >> 2, t = lane & 3;
    const int warpM = wid & 3, warpN = wid >> 2;

    const size_t arow0 = SWAP ? ((size_t)b * HWSZ + (size_t)blockIdx.y * 128)
                              : (size_t)blockIdx.y * 128;
    const size_t brow0 = SWAP ? 0 : ((size_t)b * HWSZ + (size_t)blockIdx.x * (NCH * 32));
    const __half* Ab = A_ + arow0 * KP;
    const __half* Bb = B_ + brow0 * KP;

    const uint32_t mbw = smb + MB_OFF, mbx0 = smb + MB_OFF + 8, mbx1 = smb + MB_OFF + 16;
    if (tid == 0) { mbar_init(mbw, 1); mbar_init(mbx0, 1); mbar_init(mbx1, 1); }
    __syncthreads();
    if (tid == 0) {
        expect_tx(mbw, A_BYTES);   bulk_g2s(smb,         Ab,                A_BYTES,  mbw);
        expect_tx(mbx0, XC_BYTES); bulk_g2s(smb + SM_X0, Bb,                XC_BYTES, mbx0);
        expect_tx(mbx1, XC_BYTES); bulk_g2s(smb + SM_X1, Bb + XC_ROWS * KP, XC_BYTES, mbx1);
    }

    // ldmatrix addresses (528B row stride -> conflict-free)
    const int l7 = lane & 7;
    const uint32_t rowA0 = (uint32_t)(warpM * 32 + l7 + ((lane >> 3) & 1) * 8);
    const uint32_t aA0 = smb + rowA0 * KPB + ((lane >> 4) & 1) * 16;
    const uint32_t aA1 = aA0 + 16 * KPB;
    const uint32_t rowB0 = (uint32_t)(warpN * 16 + l7 + ((lane >> 4) & 1) * 8);
    const uint32_t bB0 = rowB0 * KPB + ((lane >> 3) & 1) * 16;
    mbar_wait(mbw, 0);
    int ph0 = 0, ph1 = 0;

    #pragma unroll 1
    for (int c = 0; c < NCH; ++c) {
        const int s = c & 1;
        if (s == 0) { mbar_wait(mbx0, ph0); ph0 ^= 1; }
        else        { mbar_wait(mbx1, ph1); ph1 ^= 1; }
        const uint32_t xb = smb + SM_X0 + (uint32_t)s * XC_BYTES;

        float acc[2][2][4];
        #pragma unroll
        for (int mi = 0; mi < 2; ++mi)
            #pragma unroll
            for (int ni = 0; ni < 2; ++ni)
                #pragma unroll
                for (int u = 0; u < 4; ++u) acc[mi][ni][u] = 0.f;

        #pragma unroll
        for (int k16 = 0; k16 < 16; ++k16) {
            const uint32_t ko = (uint32_t)k16 * 32;
            uint32_t a0[4], a1[4], f0[4];
            LDSM4(a0[0], a0[1], a0[2], a0[3], aA0 + ko);
            LDSM4(a1[0], a1[1], a1[2], a1[3], aA1 + ko);
            LDSM4(f0[0], f0[1], f0[2], f0[3], xb + bB0 + ko);
            mma_f16(acc[0][0], a0, f0[0], f0[1]);
            mma_f16(acc[0][1], a0, f0[2], f0[3]);
            mma_f16(acc[1][0], a1, f0[0], f0[1]);
            mma_f16(acc[1][1], a1, f0[2], f0[3]);
        }
        __syncthreads();
        if (c + 2 < NCH && tid == 0) {
            const uint32_t mb = s ? mbx1 : mbx0;
            expect_tx(mb, XC_BYTES);
            bulk_g2s(smb + SM_X0 + (uint32_t)s * XC_BYTES,
                     Bb + (size_t)(c + 2) * XC_ROWS * KP, XC_BYTES, mb);
        }

        const int nbase = c * 32 + warpN * 16;
        #pragma unroll
        for (int mi = 0; mi < 2; ++mi) {
            #pragma unroll
            for (int r2 = 0; r2 < 2; ++r2) {
                const int m = warpM * 32 + mi * 16 + g + r2 * 8;
                if (!SWAP) {
                    // EPI_OUT: m = oc, n = pixel
                    const int oc = (int)blockIdx.y * 128 + m;
                    const float cv = cvec[b * CC + oc];
                    const size_t ybase = ((size_t)b * CC + oc) * HWSZ + (size_t)blockIdx.x * (NCH * 32);
                    #pragma unroll
                    for (int ni = 0; ni < 2; ++ni) {
                        const int n = nbase + ni * 8 + t * 2;
                        float2 r;
                        r.x = 0.5f * acc[mi][ni][r2 * 2 + 0] + cv;
                        r.y = 0.5f * acc[mi][ni][r2 * 2 + 1] + cv;
                        *(float2*)(Yf + ybase + n) = r;
                    }
                } else {
                    const size_t prow = (size_t)b * HWSZ + (size_t)blockIdx.y * 128 + m;
                    if (EPI == EPI_RELU_T) {
                        // dual relu output, KP-stride (oc split at 256)
                        #pragma unroll
                        for (int ni = 0; ni < 2; ++ni) {
                            const int oc = nbase + ni * 8 + t * 2;
                            const float* bp = bias;
                            __half* yp = Yh;
                            int o2 = oc;
                            if (oc >= 256) { bp = bias2; yp = Yh2; o2 = oc - 256; }
                            float v0 = fmaxf(acc[mi][ni][r2 * 2 + 0] + bp[o2], 0.f);
                            float v1 = fmaxf(acc[mi][ni][r2 * 2 + 1] + bp[o2 + 1], 0.f);
                            __half2 r; r.x = __float2half(v0); r.y = __float2half(v1);
                            *(__half2*)(yp + prow * KP + o2) = r;
                        }
                    } else {
                        #pragma unroll
                        for (int ni = 0; ni < 2; ++ni) {
                            const int oc = nbase + ni * 8 + t * 2;
                            float v0 = acc[mi][ni][r2 * 2 + 0] + bias[oc];
                            float v1 = acc[mi][ni][r2 * 2 + 1] + bias[oc + 1];
                            if (EPI == EPI_SIG_T) { v0 = sigmoidf_(v0); v1 = sigmoidf_(v1); }
                            else if (EPI == EPI_SIG_GATE_T) {
                                __half2 gg = *(const __half2*)(gate + prow * CC + oc);
                                v0 = sigmoidf_(v0) * (1.f - __half2float(gg.x));
                                v1 = sigmoidf_(v1) * (1.f - __half2float(gg.y));
                            }
                            __half2 r; r.x = __float2half(v0); r.y = __float2half(v1);
                            *(__half2*)(Yh + prow * OS + oc) = r;
                        }
                    }
                }
            }
        }
    }
}

// ================= windowed attention (pixel-major coalesced IO) =================
__global__ void __launch_bounds__(128)
attn_kernel(const __half* __restrict__ qkvT, const __half* __restrict__ gkT,
            const __half* __restrict__ gvT, __half* __restrict__ ft)
{
    const int w = blockIdx.x, h = blockIdx.y;
    const int b = w >> 10, wy = (w >> 5) & 31, wx = w & 31;
    const int tid = threadIdx.x;

    __shared__ float Qs[49 * 33];
    __shared__ float Ks[49 * 33];
    __shared__ float Vs[49 * 33];
    __shared__ float S [49 * 49];

    const int row0 = wy * 7, col0 = wx * 7;
    const int hoff = h * 32;

    // coalesced loads: per pixel, 64B contiguous chunks per tensor
    for (int e = tid; e < 49 * 16; e += 128) {
        const int n = e >> 4, d2 = (e & 15) << 1;
        const int hw = (row0 + n / 7) * 224 + col0 + (n % 7);
        const size_t pb = (size_t)b * HWSZ + hw;
        const __half2 q2 = *(const __half2*)(qkvT + pb * 768 + hoff + d2);
        const __half2 k2 = *(const __half2*)(qkvT + pb * 768 + 256 + hoff + d2);
        const __half2 v2 = *(const __half2*)(qkvT + pb * 768 + 512 + hoff + d2);
        const __half2 g2 = *(const __half2*)(gkT + pb * CC + hoff + d2);
        const __half2 u2 = *(const __half2*)(gvT + pb * CC + hoff + d2);
        Qs[n * 33 + d2]     = __half2float(q2.x);
        Qs[n * 33 + d2 + 1] = __half2float(q2.y);
        Ks[n * 33 + d2]     = __half2float(k2.x) * __half2float(g2.x);
        Ks[n * 33 + d2 + 1] = __half2float(k2.y) * __half2float(g2.y);
        Vs[n * 33 + d2]     = __half2float(v2.x) * __half2float(u2.x);
        Vs[n * 33 + d2 + 1] = __half2float(v2.y) * __half2float(u2.y);
    }
    __syncthreads();

    const float scale = 0.17677669529663687f;   // 32^-0.5

    // ---- QK^T: 7x4 register tiles, 91 threads ----
    if (tid < 91) {
        const int i0 = (tid / 13) * 7;
        const int j0 = (tid % 13) * 4;
        float acc[7][4];
        #pragma unroll
        for (int r = 0; r < 7; ++r)
            #pragma unroll
            for (int c2 = 0; c2 < 4; ++c2) acc[r][c2] = 0.f;
        int jc[4];
        #pragma unroll
        for (int c2 = 0; c2 < 4; ++c2) jc[c2] = min(j0 + c2, 48);
        #pragma unroll
        for (int d = 0; d < 32; ++d) {
            float kv[4];
            #pragma unroll
            for (int c2 = 0; c2 < 4; ++c2) kv[c2] = Ks[jc[c2] * 33 + d];
            #pragma unroll
            for (int r = 0; r < 7; ++r) {
                const float qv = Qs[(i0 + r) * 33 + d];
                #pragma unroll
                for (int c2 = 0; c2 < 4; ++c2) acc[r][c2] += qv * kv[c2];
            }
        }
        #pragma unroll
        for (int r = 0; r < 7; ++r)
            #pragma unroll
            for (int c2 = 0; c2 < 4; ++c2)
                if (j0 + c2 < 49) S[(i0 + r) * 49 + j0 + c2] = acc[r][c2] * scale;
    }
    __syncthreads();

    if (tid < 49) {
        float m = -1e30f;
        for (int j = 0; j < 49; ++j) m = fmaxf(m, S[tid * 49 + j]);
        float sum = 0.f;
        for (int j = 0; j < 49; ++j) {
            float ev = __expf(S[tid * 49 + j] - m);
            S[tid * 49 + j] = ev;
            sum += ev;
        }
        const float inv = 1.f / sum;
        for (int j = 0; j < 49; ++j) S[tid * 49 + j] *= inv;
    }
    __syncthreads();

    // ---- S @ V: 4x4 register tiles, 104 threads ----
    if (tid < 104) {
        const int n0 = (tid / 8) * 4;
        const int d0 = (tid & 7) * 4;
        float acc[4][4];
        #pragma unroll
        for (int r = 0; r < 4; ++r)
            #pragma unroll
            for (int c2 = 0; c2 < 4; ++c2) acc[r][c2] = 0.f;
        int nr[4];
        #pragma unroll
        for (int r = 0; r < 4; ++r) nr[r] = min(n0 + r, 48);
        #pragma unroll 7
        for (int m2 = 0; m2 < 49; ++m2) {
            float vv[4];
            #pragma unroll
            for (int c2 = 0; c2 < 4; ++c2) vv[c2] = Vs[m2 * 33 + d0 + c2];
            #pragma unroll
            for (int r = 0; r < 4; ++r) {
                const float sv = S[nr[r] * 49 + m2];
                #pragma unroll
                for (int c2 = 0; c2 < 4; ++c2) acc[r][c2] += sv * vv[c2];
            }
        }
        #pragma unroll
        for (int r = 0; r < 4; ++r) {
            const int n = n0 + r;
            if (n < 49) {
                const int hw = (row0 + n / 7) * 224 + col0 + (n % 7);
                #pragma unroll
                for (int c2 = 0; c2 < 4; ++c2)
                    ft[((size_t)b * HWSZ + hw) * KP + hoff + d0 + c2] = __float2half(acc[r][c2]);
            }
        }
    }
}

// ================= launcher =================
extern "C" void kernel_launch(void* const* d_in, const int* in_sizes, int n_in,
                              void* d_out, int out_size) {
    (void)in_sizes; (void)n_in; (void)out_size;
    const float* G    = (const float*)d_in[0];
    const float* Vin  = (const float*)d_in[2];
    const float* Z    = (const float*)d_in[3];
    const float* Wqkv = (const float*)d_in[4];
    const float* bqkv = (const float*)d_in[5];
    const float* Wout = (const float*)d_in[6];
    const float* bout = (const float*)d_in[7];
    const float* Wk1  = (const float*)d_in[8];
    const float* bk1  = (const float*)d_in[9];
    const float* Wk2  = (const float*)d_in[10];
    const float* bk2  = (const float*)d_in[11];
    const float* Wv1  = (const float*)d_in[12];
    const float* bv1  = (const float*)d_in[13];
    const float* Wv2  = (const float*)d_in[14];
    const float* bv2  = (const float*)d_in[15];
    const float* Wp1  = (const float*)d_in[16];
    const float* bp1  = (const float*)d_in[17];
    const float* Wp2  = (const float*)d_in[18];
    const float* bp2  = (const float*)d_in[19];
    float* out = (float*)d_out;

    __half *qkvT, *psiT, *gkT, *gvT, *ta, *tb, *tc, *td, *wp;
    float *gmean, *cvec;
    cudaGetSymbolAddress((void**)&qkvT,  g_qkv);
    cudaGetSymbolAddress((void**)&psiT,  g_psi);
    cudaGetSymbolAddress((void**)&gkT,   g_gk);
    cudaGetSymbolAddress((void**)&gvT,   g_gv);
    cudaGetSymbolAddress((void**)&gmean, g_mean);
    cudaGetSymbolAddress((void**)&cvec,  g_cvec);
    cudaGetSymbolAddress((void**)&ta,    g_ta);
    cudaGetSymbolAddress((void**)&tb,    g_tb);
    cudaGetSymbolAddress((void**)&tc,    g_tc);
    cudaGetSymbolAddress((void**)&td,    g_td);
    cudaGetSymbolAddress((void**)&wp,    g_wp);

    cudaFuncSetAttribute(gemm_bulk<EPI_QKV_T,      true,  24>, cudaFuncAttributeMaxDynamicSharedMemorySize, SMEM_TOTAL);
    cudaFuncSetAttribute(gemm_bulk<EPI_RELU_T,     true,  16>, cudaFuncAttributeMaxDynamicSharedMemorySize, SMEM_TOTAL);
    cudaFuncSetAttribute(gemm_bulk<EPI_SIG_T,      true,  8>,  cudaFuncAttributeMaxDynamicSharedMemorySize, SMEM_TOTAL);
    cudaFuncSetAttribute(gemm_bulk<EPI_SIG_GATE_T, true,  8>,  cudaFuncAttributeMaxDynamicSharedMemorySize, SMEM_TOTAL);
    cudaFuncSetAttribute(gemm_bulk<EPI_OUT,        false, 8>,  cudaFuncAttributeMaxDynamicSharedMemorySize, SMEM_TOTAL);

    // weight layout (rows of KP)
    __half* wQKV = wp;
    __half* wKV1 = wp + (size_t)768  * KP;   // k1 rows [0,256), v1 rows [256,512)
    __half* wK2  = wp + (size_t)1280 * KP;
    __half* wV2  = wp + (size_t)1536 * KP;
    __half* wP2  = wp + (size_t)1792 * KP;
    __half* wOUT = wp + (size_t)2048 * KP;

    const dim3 tgrid(HWSZ / 32, CC / 32, BB), tblk(32, 8);
    const dim3 gS(1, 392, BB);    // SWAP: px-tiles(128) on y
    const dim3 gO(196, 2, BB);    // !SWAP out: px-tiles(256) x oc-tiles(128) x B

    mean_kernel<<<1024, 256>>>(G, gmean);                       // 0
    cvec_kernel<<<4, 256>>>(Wout, bout, gmean, cvec);           // 1
    wconv<<<768, 128>>>(Wqkv, wQKV);                            // 2
    tconv<<<tgrid, tblk>>>(G, ta);                              // 3
    // qkvT = (Wqkv @ G + bqkv)^T -> [b][px][768]               // 4 <-- profiled slot
    gemm_bulk<EPI_QKV_T, true, 24><<<gS, 256, SMEM_TOTAL>>>(
        ta, wQKV, bqkv, nullptr, nullptr, nullptr, qkvT, 768, nullptr, nullptr);

    tconv<<<tgrid, tblk>>>(Z, tb);
    wconv<<<256, 128>>>(Wk1,  wKV1);
    wconv<<<256, 128>>>(Wv1,  wKV1 + (size_t)256 * KP);
    wconv<<<256, 128>>>(Wk2,  wK2);
    wconv<<<256, 128>>>(Wv2,  wV2);
    wconv<<<256, 128>>>(Wp2,  wP2);
    wconv<<<256, 128>>>(Wout, wOUT);
    psix<<<dim3(HWSZ / 8, BB), 256>>>(Vin, Wp1, bp1, tc);

    // psiT = sigmoid(Wp2 @ relu(v*wp1+bp1) + bp2)^T -> [b][px][256]
    gemm_bulk<EPI_SIG_T, true, 8><<<gS, 256, SMEM_TOTAL>>>(
        tc, wP2, bp2, nullptr, nullptr, nullptr, psiT, 256, nullptr, nullptr);

    // fused h_k / h_v = relu(W{k1,v1}@Z + b)^T -> tc, td ([px][KP])
    gemm_bulk<EPI_RELU_T, true, 16><<<gS, 256, SMEM_TOTAL>>>(
        tb, wKV1, bk1, nullptr, nullptr, nullptr, tc, KP, bv1, td);

    // gkT = sigmoid(Wk2@h_k+bk2)^T * (1-psiT); gvT likewise
    gemm_bulk<EPI_SIG_GATE_T, true, 8><<<gS, 256, SMEM_TOTAL>>>(
        tc, wK2, bk2, psiT, nullptr, nullptr, gkT, 256, nullptr, nullptr);
    gemm_bulk<EPI_SIG_GATE_T, true, 8><<<gS, 256, SMEM_TOTAL>>>(
        td, wV2, bv2, psiT, nullptr, nullptr, gvT, 256, nullptr, nullptr);

    // attention -> ft ([px][KP], reuses tc)
    attn_kernel<<<dim3(4096, 8), 128>>>(qkvT, gkT, gvT, tc);

    // out = 0.5 * Wout @ f + cvec -> fp32 [b][256][HW]
    gemm_bulk<EPI_OUT, false, 8><<<gO, 256, SMEM_TOTAL>>>(
        wOUT, tc, nullptr, nullptr, cvec, out, nullptr, 256, nullptr, nullptr);
}